// round 1
// baseline (speedup 1.0000x reference)
#include <cuda_runtime.h>
#include <math.h>
#include <math_constants.h>

#define NP   30000
#define DIN  1536
#define DOUT 256
#define NHEAD 2
#define CHD  128
#define NE   320000
#define NEG_SLOPE 0.2f

// ---------------- scratch (device globals; no cudaMalloc allowed) -----------
__device__ float g_xl1[(size_t)NP * DOUT];
__device__ float g_xr1[(size_t)NP * DOUT];
__device__ float g_res[(size_t)NP * DOUT];
__device__ float g_gat[(size_t)NP * DOUT];
__device__ float g_h1 [(size_t)NP * DOUT];
__device__ float g_xl2[(size_t)NP * DOUT];
__device__ float g_xr2[(size_t)NP * DOUT];

__device__ int g_deg[NP];
__device__ int g_off[NP + 1];
__device__ int g_cur[NP];
__device__ int g_srcs[NE];

// ---------------- fp32 tiled GEMM: Y = X[M,K] @ W[K,N] + b ------------------
#define BM 128
#define BN 128
#define BK 8
#define TM 8
#define TN 8

__global__ __launch_bounds__(256, 2)
void sgemm_bias(const float* __restrict__ X, const float* __restrict__ W,
                const float* __restrict__ b, float* __restrict__ Y,
                int M, int K, int N) {
    __shared__ float As[BK][BM];
    __shared__ float Bs[BK][BN];

    const int tid = threadIdx.x;
    const int bm = blockIdx.y * BM;
    const int bn = blockIdx.x * BN;

    const int arow = tid >> 1;          // 0..127
    const int acol = (tid & 1) * 4;     // 0 or 4
    const int brow = tid >> 5;          // 0..7
    const int bcol = (tid & 31) * 4;    // 0..124

    const int tm = (tid >> 4) * TM;     // 0..120
    const int tn = (tid & 15) * TN;     // 0..120

    float acc[TM][TN];
#pragma unroll
    for (int i = 0; i < TM; i++)
#pragma unroll
        for (int j = 0; j < TN; j++) acc[i][j] = 0.f;

    for (int k0 = 0; k0 < K; k0 += BK) {
        float4 av;
        if (bm + arow < M)
            av = *reinterpret_cast<const float4*>(X + (size_t)(bm + arow) * K + k0 + acol);
        else
            av = make_float4(0.f, 0.f, 0.f, 0.f);
        As[acol + 0][arow] = av.x;
        As[acol + 1][arow] = av.y;
        As[acol + 2][arow] = av.z;
        As[acol + 3][arow] = av.w;

        float4 bv = *reinterpret_cast<const float4*>(W + (size_t)(k0 + brow) * N + bn + bcol);
        *reinterpret_cast<float4*>(&Bs[brow][bcol]) = bv;

        __syncthreads();

#pragma unroll
        for (int k = 0; k < BK; k++) {
            float a[TM], bb[TN];
#pragma unroll
            for (int i = 0; i < TM; i++) a[i] = As[k][tm + i];
#pragma unroll
            for (int j = 0; j < TN; j++) bb[j] = Bs[k][tn + j];
#pragma unroll
            for (int i = 0; i < TM; i++)
#pragma unroll
                for (int j = 0; j < TN; j++) acc[i][j] = fmaf(a[i], bb[j], acc[i][j]);
        }
        __syncthreads();
    }

#pragma unroll
    for (int i = 0; i < TM; i++) {
        int row = bm + tm + i;
        if (row < M) {
#pragma unroll
            for (int j = 0; j < TN; j++) {
                int col = bn + tn + j;
                Y[(size_t)row * N + col] = acc[i][j] + b[col];
            }
        }
    }
}

// ---------------- CSR build --------------------------------------------------
__global__ void zero_deg_kernel() {
    int i = blockIdx.x * blockDim.x + threadIdx.x;
    if (i < NP) g_deg[i] = 0;
}

__global__ void count_deg_kernel(const int* __restrict__ dst) {
    int e = blockIdx.x * blockDim.x + threadIdx.x;
    if (e < NE) atomicAdd(&g_deg[dst[e]], 1);
}

__global__ void build_offsets_kernel() {
    __shared__ int ssum[1024];
    const int tid = threadIdx.x;
    const int CHK = (NP + 1023) / 1024;   // 30
    int start = tid * CHK;
    int end = start + CHK; if (end > NP) end = NP;
    if (start > NP) start = NP;

    int s = 0;
    for (int i = start; i < end; i++) s += g_deg[i];
    ssum[tid] = s;
    __syncthreads();

    // Hillis-Steele inclusive scan over 1024 partials
    for (int o = 1; o < 1024; o <<= 1) {
        int v = (tid >= o) ? ssum[tid - o] : 0;
        __syncthreads();
        ssum[tid] += v;
        __syncthreads();
    }

    int run = (tid == 0) ? 0 : ssum[tid - 1];   // exclusive base
    for (int i = start; i < end; i++) {
        g_off[i] = run;
        g_cur[i] = run;
        run += g_deg[i];
    }
    if (tid == 1023) g_off[NP] = ssum[1023];
}

__global__ void scatter_edges_kernel(const int* __restrict__ src,
                                     const int* __restrict__ dst) {
    int e = blockIdx.x * blockDim.x + threadIdx.x;
    if (e < NE) {
        int d = dst[e];
        int pos = atomicAdd(&g_cur[d], 1);
        g_srcs[pos] = src[e];
    }
}

// ---------------- GATv2 gather with online softmax (warp per node) ----------
__global__ void gat_gather_kernel(const float* __restrict__ xl,
                                  const float* __restrict__ xr,
                                  const float* __restrict__ att,
                                  const float* __restrict__ bias,
                                  float* __restrict__ out) {
    int w = (blockIdx.x * blockDim.x + threadIdx.x) >> 5;
    int lane = threadIdx.x & 31;
    if (w >= NP) return;
    const int i = w;
    const int cbase = lane * 8;

    float xri[8], atv[8];
    {
        float4 a0 = *reinterpret_cast<const float4*>(xr + (size_t)i * DOUT + cbase);
        float4 a1 = *reinterpret_cast<const float4*>(xr + (size_t)i * DOUT + cbase + 4);
        xri[0]=a0.x; xri[1]=a0.y; xri[2]=a0.z; xri[3]=a0.w;
        xri[4]=a1.x; xri[5]=a1.y; xri[6]=a1.z; xri[7]=a1.w;
        float4 t0 = *reinterpret_cast<const float4*>(att + cbase);
        float4 t1 = *reinterpret_cast<const float4*>(att + cbase + 4);
        atv[0]=t0.x; atv[1]=t0.y; atv[2]=t0.z; atv[3]=t0.w;
        atv[4]=t1.x; atv[5]=t1.y; atv[6]=t1.z; atv[7]=t1.w;
    }

    float m = -CUDART_INF_F;
    float s = 0.f;
    float acc[8];
#pragma unroll
    for (int k = 0; k < 8; k++) acc[k] = 0.f;

    const int beg = g_off[i];
    const int end = g_off[i + 1];

    int j = i;           // self loop processed first
    int ptr = beg;
    while (true) {
        float xlj[8];
        {
            float4 a0 = *reinterpret_cast<const float4*>(xl + (size_t)j * DOUT + cbase);
            float4 a1 = *reinterpret_cast<const float4*>(xl + (size_t)j * DOUT + cbase + 4);
            xlj[0]=a0.x; xlj[1]=a0.y; xlj[2]=a0.z; xlj[3]=a0.w;
            xlj[4]=a1.x; xlj[5]=a1.y; xlj[6]=a1.z; xlj[7]=a1.w;
        }
        float p = 0.f;
#pragma unroll
        for (int k = 0; k < 8; k++) {
            float t = xlj[k] + xri[k];
            t = (t > 0.f) ? t : NEG_SLOPE * t;
            p = fmaf(atv[k], t, p);
        }
        // reduce within half-warp (one head = 16 lanes = 128 channels)
        p += __shfl_xor_sync(0xffffffffu, p, 8, 16);
        p += __shfl_xor_sync(0xffffffffu, p, 4, 16);
        p += __shfl_xor_sync(0xffffffffu, p, 2, 16);
        p += __shfl_xor_sync(0xffffffffu, p, 1, 16);

        float e  = p;
        float nm = fmaxf(m, e);
        float sc = __expf(m - nm);   // exp(-inf)=0 on first edge
        float wgt = __expf(e - nm);
        s = s * sc + wgt;
#pragma unroll
        for (int k = 0; k < 8; k++) acc[k] = fmaf(acc[k], sc, wgt * xlj[k]);
        m = nm;

        if (ptr >= end) break;
        j = g_srcs[ptr++];
    }

    float inv = 1.f / s;
#pragma unroll
    for (int k = 0; k < 8; k++)
        out[(size_t)i * DOUT + cbase + k] = acc[k] * inv + bias[cbase + k];
}

// ---------------- LN + ELU + residual (warp per row) ------------------------
__device__ __forceinline__ void ln_elu_row(const float* __restrict__ in,
                                           const float* __restrict__ g,
                                           const float* __restrict__ b,
                                           int lane, float* v /*8 out*/) {
    const int cbase = lane * 8;
    float4 a0 = *reinterpret_cast<const float4*>(in + cbase);
    float4 a1 = *reinterpret_cast<const float4*>(in + cbase + 4);
    v[0]=a0.x; v[1]=a0.y; v[2]=a0.z; v[3]=a0.w;
    v[4]=a1.x; v[5]=a1.y; v[6]=a1.z; v[7]=a1.w;
    float s = 0.f, s2 = 0.f;
#pragma unroll
    for (int k = 0; k < 8; k++) { s += v[k]; s2 = fmaf(v[k], v[k], s2); }
#pragma unroll
    for (int o = 16; o >= 1; o >>= 1) {
        s  += __shfl_xor_sync(0xffffffffu, s,  o);
        s2 += __shfl_xor_sync(0xffffffffu, s2, o);
    }
    float mu  = s * (1.f / 256.f);
    float var = s2 * (1.f / 256.f) - mu * mu;
    float rs  = rsqrtf(var + 1e-5f);
#pragma unroll
    for (int k = 0; k < 8; k++) {
        int c = cbase + k;
        float t = (v[k] - mu) * rs * g[c] + b[c];
        v[k] = (t > 0.f) ? t : expm1f(t);
    }
}

__global__ void post1_kernel(const float* __restrict__ gat,
                             const float* __restrict__ res,
                             const float* __restrict__ lng,
                             const float* __restrict__ lnb,
                             float* __restrict__ h1) {
    int w = (blockIdx.x * blockDim.x + threadIdx.x) >> 5;
    int lane = threadIdx.x & 31;
    if (w >= NP) return;
    float v[8];
    ln_elu_row(gat + (size_t)w * DOUT, lng, lnb, lane, v);
    const int cbase = lane * 8;
#pragma unroll
    for (int k = 0; k < 8; k++) {
        size_t idx = (size_t)w * DOUT + cbase + k;
        h1[idx] = v[k] + res[idx];
    }
}

__global__ void post2_kernel(const float* __restrict__ gat,
                             const float* __restrict__ h1,
                             const float* __restrict__ lng,
                             const float* __restrict__ lnb,
                             float* __restrict__ out) {
    int w = (blockIdx.x * blockDim.x + threadIdx.x) >> 5;
    int lane = threadIdx.x & 31;
    if (w >= NP) return;
    float v[8];
    ln_elu_row(gat + (size_t)w * DOUT, lng, lnb, lane, v);
    const int cbase = lane * 8;
#pragma unroll
    for (int k = 0; k < 8; k++) {
        size_t idx = (size_t)w * DOUT + cbase + k;
        float h1v = h1[idx];
        float h2v = v[k] + h1v;
        out[idx] = fmaxf(h1v, h2v);
    }
}

// ---------------- launch -----------------------------------------------------
extern "C" void kernel_launch(void* const* d_in, const int* in_sizes, int n_in,
                              void* d_out, int out_size) {
    const float* x     = (const float*)d_in[0];
    const int*   ei    = (const int*)  d_in[1];   // (2, E): row0 src, row1 dst
    const float* W1l   = (const float*)d_in[2];
    const float* b1l   = (const float*)d_in[3];
    const float* W1r   = (const float*)d_in[4];
    const float* b1r   = (const float*)d_in[5];
    const float* att1  = (const float*)d_in[6];
    const float* bias1 = (const float*)d_in[7];
    const float* W2l   = (const float*)d_in[8];
    const float* b2l   = (const float*)d_in[9];
    const float* W2r   = (const float*)d_in[10];
    const float* b2r   = (const float*)d_in[11];
    const float* att2  = (const float*)d_in[12];
    const float* bias2 = (const float*)d_in[13];
    const float* ln1g  = (const float*)d_in[14];
    const float* ln1b  = (const float*)d_in[15];
    const float* ln2g  = (const float*)d_in[16];
    const float* ln2b  = (const float*)d_in[17];
    const float* resW  = (const float*)d_in[18];
    const float* resb  = (const float*)d_in[19];
    float* out = (float*)d_out;

    const int* e_src = ei;
    const int* e_dst = ei + NE;

    float *xl1, *xr1, *res, *gat, *h1, *xl2, *xr2;
    cudaGetSymbolAddress((void**)&xl1, g_xl1);
    cudaGetSymbolAddress((void**)&xr1, g_xr1);
    cudaGetSymbolAddress((void**)&res, g_res);
    cudaGetSymbolAddress((void**)&gat, g_gat);
    cudaGetSymbolAddress((void**)&h1,  g_h1);
    cudaGetSymbolAddress((void**)&xl2, g_xl2);
    cudaGetSymbolAddress((void**)&xr2, g_xr2);

    dim3 gemmGrid1(DOUT / BN, (NP + BM - 1) / BM);   // (2, 235)

    // layer-1 projections (+ residual projection)
    sgemm_bias<<<gemmGrid1, 256>>>(x, W1l, b1l, xl1, NP, DIN, DOUT);
    sgemm_bias<<<gemmGrid1, 256>>>(x, W1r, b1r, xr1, NP, DIN, DOUT);
    sgemm_bias<<<gemmGrid1, 256>>>(x, resW, resb, res, NP, DIN, DOUT);

    // CSR by destination (self loops handled analytically in the gather)
    zero_deg_kernel<<<(NP + 255) / 256, 256>>>();
    count_deg_kernel<<<(NE + 255) / 256, 256>>>(e_dst);
    build_offsets_kernel<<<1, 1024>>>();
    scatter_edges_kernel<<<(NE + 255) / 256, 256>>>(e_src, e_dst);

    // layer 1 attention + post
    int gatherBlocks = (NP * 32 + 255) / 256;
    gat_gather_kernel<<<gatherBlocks, 256>>>(xl1, xr1, att1, bias1, gat);
    post1_kernel<<<gatherBlocks, 256>>>(gat, res, ln1g, ln1b, h1);

    // layer-2 projections
    sgemm_bias<<<gemmGrid1, 256>>>(h1, W2l, b2l, xl2, NP, DOUT, DOUT);
    sgemm_bias<<<gemmGrid1, 256>>>(h1, W2r, b2r, xr2, NP, DOUT, DOUT);

    // layer 2 attention + post + JK-max
    gat_gather_kernel<<<gatherBlocks, 256>>>(xl2, xr2, att2, bias2, gat);
    post2_kernel<<<gatherBlocks, 256>>>(gat, h1, ln2g, ln2b, out);
}

// round 2
// speedup vs baseline: 2.0313x; 2.0313x over previous
#include <cuda_runtime.h>
#include <cuda_bf16.h>
#include <mma.h>
#include <math.h>
#include <math_constants.h>

using namespace nvcuda;

#define NP    30000
#define MPAD  30080          // 235 * 128
#define DIN   1536
#define DOUT  256
#define NE    320000
#define NEG_SLOPE 0.2f
#define N1    768            // xl1 | xr1 | res
#define N2    512            // xl2 | xr2

// ---------------- scratch (device globals; no cudaMalloc allowed) -----------
__device__ __align__(256) __nv_bfloat16 g_xhi[(size_t)MPAD * DIN];
__device__ __align__(256) __nv_bfloat16 g_xlo[(size_t)MPAD * DIN];
__device__ __align__(256) __nv_bfloat16 g_w1hi[(size_t)DIN * N1];
__device__ __align__(256) __nv_bfloat16 g_w1lo[(size_t)DIN * N1];
__device__ __align__(256) __nv_bfloat16 g_w2hi[(size_t)DOUT * N2];
__device__ __align__(256) __nv_bfloat16 g_w2lo[(size_t)DOUT * N2];
__device__ __align__(256) float g_y1[(size_t)MPAD * N1];
__device__ __align__(256) float g_y2[(size_t)MPAD * N2];
__device__ __align__(256) float g_h1[(size_t)MPAD * DOUT];
__device__ __align__(256) __nv_bfloat16 g_h1hi[(size_t)MPAD * DOUT];
__device__ __align__(256) __nv_bfloat16 g_h1lo[(size_t)MPAD * DOUT];
__device__ __align__(256) float g_gat[(size_t)NP * DOUT];

__device__ int g_deg[NP];
__device__ int g_off[NP + 1];
__device__ int g_cur[NP];
__device__ int g_srcs[NE];

// ---------------- helpers ----------------------------------------------------
__device__ __forceinline__ void split_bf16(float v, __nv_bfloat16& h, __nv_bfloat16& l) {
    h = __float2bfloat16(v);
    l = __float2bfloat16(v - __bfloat162float(h));
}

__device__ __forceinline__ void cp16(void* dst, const void* src) {
    unsigned saddr = (unsigned)__cvta_generic_to_shared(dst);
    asm volatile("cp.async.cg.shared.global [%0], [%1], 16;\n" :: "r"(saddr), "l"(src));
}

// ---------------- input conversion kernels -----------------------------------
__global__ void convert_x_kernel(const float* __restrict__ x) {
    size_t i4 = (size_t)blockIdx.x * blockDim.x + threadIdx.x;
    const size_t tot = (size_t)MPAD * DIN / 4;
    if (i4 >= tot) return;
    size_t row = i4 / (DIN / 4);
    float4 v;
    if (row < NP) v = *reinterpret_cast<const float4*>(x + i4 * 4);
    else          v = make_float4(0.f, 0.f, 0.f, 0.f);
    __nv_bfloat16 h, l;
    size_t o = i4 * 4;
    split_bf16(v.x, h, l); g_xhi[o+0] = h; g_xlo[o+0] = l;
    split_bf16(v.y, h, l); g_xhi[o+1] = h; g_xlo[o+1] = l;
    split_bf16(v.z, h, l); g_xhi[o+2] = h; g_xlo[o+2] = l;
    split_bf16(v.w, h, l); g_xhi[o+3] = h; g_xlo[o+3] = l;
}

__global__ void pack_w1_kernel(const float* __restrict__ W1l,
                               const float* __restrict__ W1r,
                               const float* __restrict__ resW) {
    int i4 = blockIdx.x * blockDim.x + threadIdx.x;          // over DIN*N1/4
    if (i4 >= DIN * N1 / 4) return;
    int k = i4 / (N1 / 4);
    int c = (i4 % (N1 / 4)) * 4;
    const float* W = (c < 256) ? W1l : (c < 512 ? W1r : resW);
    int cc = c & 255;
    float4 v = *reinterpret_cast<const float4*>(W + (size_t)k * 256 + cc);
    size_t o = (size_t)k * N1 + c;
    __nv_bfloat16 h, l;
    split_bf16(v.x, h, l); g_w1hi[o+0] = h; g_w1lo[o+0] = l;
    split_bf16(v.y, h, l); g_w1hi[o+1] = h; g_w1lo[o+1] = l;
    split_bf16(v.z, h, l); g_w1hi[o+2] = h; g_w1lo[o+2] = l;
    split_bf16(v.w, h, l); g_w1hi[o+3] = h; g_w1lo[o+3] = l;
}

__global__ void pack_w2_kernel(const float* __restrict__ W2l,
                               const float* __restrict__ W2r) {
    int i4 = blockIdx.x * blockDim.x + threadIdx.x;          // over DOUT*N2/4
    if (i4 >= DOUT * N2 / 4) return;
    int k = i4 / (N2 / 4);
    int c = (i4 % (N2 / 4)) * 4;
    const float* W = (c < 256) ? W2l : W2r;
    int cc = c & 255;
    float4 v = *reinterpret_cast<const float4*>(W + (size_t)k * 256 + cc);
    size_t o = (size_t)k * N2 + c;
    __nv_bfloat16 h, l;
    split_bf16(v.x, h, l); g_w2hi[o+0] = h; g_w2lo[o+0] = l;
    split_bf16(v.y, h, l); g_w2hi[o+1] = h; g_w2lo[o+1] = l;
    split_bf16(v.z, h, l); g_w2hi[o+2] = h; g_w2lo[o+2] = l;
    split_bf16(v.w, h, l); g_w2hi[o+3] = h; g_w2lo[o+3] = l;
}

// ---------------- bf16x3 tensor-core GEMM ------------------------------------
// Y[M,N] = (Ahi+Alo)[M,K] @ (Bhi+Blo)[K,N], dropping lo*lo term.
// CTA tile 128x128, BK=32, 8 warps (2M x 4N), warp tile 64x32, double-buffered.
#define GBM 128
#define GBN 128
#define GBK 32
#define LDA 40     // 32 + 8 pad (bf16 elems)
#define LDB 136    // 128 + 8 pad
#define SMEM_A_ELEMS (2 * 2 * 128 * LDA)
#define SMEM_B_ELEMS (2 * 2 * 32 * LDB)
#define GEMM_SMEM_BYTES ((SMEM_A_ELEMS + SMEM_B_ELEMS) * 2)

__device__ __forceinline__ void gemm_prefetch(
    const __nv_bfloat16* __restrict__ Ahi, const __nv_bfloat16* __restrict__ Alo,
    const __nv_bfloat16* __restrict__ Bhi, const __nv_bfloat16* __restrict__ Blo,
    __nv_bfloat16* a0, __nv_bfloat16* a1, __nv_bfloat16* b0, __nv_bfloat16* b1,
    int bm, int bn, int k0, int K, int N, int tid)
{
    // A: 128x32 bf16 = 512 x 16B chunks; thread -> chunks {tid, tid+256}
    int ar = tid >> 2;
    int ac = (tid & 3) * 8;
#pragma unroll
    for (int h = 0; h < 2; h++) {
        int row = ar + h * 64;
        size_t g = (size_t)(bm + row) * K + k0 + ac;
        int s = row * LDA + ac;
        cp16(a0 + s, Ahi + g);
        cp16(a1 + s, Alo + g);
    }
    // B: 32x128 bf16 = 512 x 16B chunks
    int br = tid >> 4;
    int bc = (tid & 15) * 8;
#pragma unroll
    for (int h = 0; h < 2; h++) {
        int row = br + h * 16;
        size_t g = (size_t)(k0 + row) * N + bn + bc;
        int s = row * LDB + bc;
        cp16(b0 + s, Bhi + g);
        cp16(b1 + s, Blo + g);
    }
    asm volatile("cp.async.commit_group;\n");
}

__global__ __launch_bounds__(256)
void gemm_bf16x3(const __nv_bfloat16* __restrict__ Ahi,
                 const __nv_bfloat16* __restrict__ Alo,
                 const __nv_bfloat16* __restrict__ Bhi,
                 const __nv_bfloat16* __restrict__ Blo,
                 float* __restrict__ Y, int K, int N)
{
    extern __shared__ char smem[];
    __nv_bfloat16* sA = (__nv_bfloat16*)smem;
    __nv_bfloat16* sB = (__nv_bfloat16*)(smem + SMEM_A_ELEMS * 2);

    const int tid = threadIdx.x;
    const int bm = blockIdx.y * GBM;
    const int bn = blockIdx.x * GBN;
    const int warp = tid >> 5;
    const int wm = (warp >> 2) * 64;
    const int wn = (warp & 3) * 32;

    wmma::fragment<wmma::accumulator, 16, 16, 16, float> acc[4][2];
#pragma unroll
    for (int i = 0; i < 4; i++)
#pragma unroll
        for (int j = 0; j < 2; j++) wmma::fill_fragment(acc[i][j], 0.f);

    const int KT = K / GBK;
    gemm_prefetch(Ahi, Alo, Bhi, Blo,
                  sA, sA + 128 * LDA, sB, sB + 32 * LDB,
                  bm, bn, 0, K, N, tid);

    for (int kt = 0; kt < KT; kt++) {
        asm volatile("cp.async.wait_group 0;\n");
        __syncthreads();
        if (kt + 1 < KT) {
            int s = (kt + 1) & 1;
            gemm_prefetch(Ahi, Alo, Bhi, Blo,
                          sA + (s * 2 + 0) * 128 * LDA, sA + (s * 2 + 1) * 128 * LDA,
                          sB + (s * 2 + 0) * 32 * LDB,  sB + (s * 2 + 1) * 32 * LDB,
                          bm, bn, (kt + 1) * GBK, K, N, tid);
        }
        int s = kt & 1;
        const __nv_bfloat16* a0 = sA + (s * 2 + 0) * 128 * LDA;
        const __nv_bfloat16* a1 = sA + (s * 2 + 1) * 128 * LDA;
        const __nv_bfloat16* b0 = sB + (s * 2 + 0) * 32 * LDB;
        const __nv_bfloat16* b1 = sB + (s * 2 + 1) * 32 * LDB;

#pragma unroll
        for (int ks = 0; ks < 2; ks++) {
            wmma::fragment<wmma::matrix_a, 16, 16, 16, __nv_bfloat16, wmma::row_major> fahi[4], falo[4];
            wmma::fragment<wmma::matrix_b, 16, 16, 16, __nv_bfloat16, wmma::row_major> fbhi[2], fblo[2];
#pragma unroll
            for (int i = 0; i < 4; i++) {
                wmma::load_matrix_sync(fahi[i], a0 + (wm + i * 16) * LDA + ks * 16, LDA);
                wmma::load_matrix_sync(falo[i], a1 + (wm + i * 16) * LDA + ks * 16, LDA);
            }
#pragma unroll
            for (int j = 0; j < 2; j++) {
                wmma::load_matrix_sync(fbhi[j], b0 + ks * 16 * LDB + wn + j * 16, LDB);
                wmma::load_matrix_sync(fblo[j], b1 + ks * 16 * LDB + wn + j * 16, LDB);
            }
#pragma unroll
            for (int i = 0; i < 4; i++)
#pragma unroll
                for (int j = 0; j < 2; j++) {
                    wmma::mma_sync(acc[i][j], fahi[i], fbhi[j], acc[i][j]);
                    wmma::mma_sync(acc[i][j], falo[i], fbhi[j], acc[i][j]);
                    wmma::mma_sync(acc[i][j], fahi[i], fblo[j], acc[i][j]);
                }
        }
    }

#pragma unroll
    for (int i = 0; i < 4; i++)
#pragma unroll
        for (int j = 0; j < 2; j++)
            wmma::store_matrix_sync(Y + (size_t)(bm + wm + i * 16) * N + bn + wn + j * 16,
                                    acc[i][j], N, wmma::mem_row_major);
}

// ---------------- CSR build --------------------------------------------------
__global__ void zero_deg_kernel() {
    int i = blockIdx.x * blockDim.x + threadIdx.x;
    if (i < NP) g_deg[i] = 0;
}

__global__ void count_deg_kernel(const int* __restrict__ dst) {
    int e = blockIdx.x * blockDim.x + threadIdx.x;
    if (e < NE) atomicAdd(&g_deg[dst[e]], 1);
}

__global__ void build_offsets_kernel() {
    __shared__ int ssum[1024];
    const int tid = threadIdx.x;
    const int CHK = (NP + 1023) / 1024;
    int start = tid * CHK;
    int end = start + CHK; if (end > NP) end = NP;
    if (start > NP) start = NP;

    int s = 0;
    for (int i = start; i < end; i++) s += g_deg[i];
    ssum[tid] = s;
    __syncthreads();
    for (int o = 1; o < 1024; o <<= 1) {
        int v = (tid >= o) ? ssum[tid - o] : 0;
        __syncthreads();
        ssum[tid] += v;
        __syncthreads();
    }
    int run = (tid == 0) ? 0 : ssum[tid - 1];
    for (int i = start; i < end; i++) {
        g_off[i] = run;
        g_cur[i] = run;
        run += g_deg[i];
    }
    if (tid == 1023) g_off[NP] = ssum[1023];
}

__global__ void scatter_edges_kernel(const int* __restrict__ src,
                                     const int* __restrict__ dst) {
    int e = blockIdx.x * blockDim.x + threadIdx.x;
    if (e < NE) {
        int d = dst[e];
        int pos = atomicAdd(&g_cur[d], 1);
        g_srcs[pos] = src[e];
    }
}

// ---------------- GATv2 gather with online softmax (warp per node) ----------
__global__ void gat_gather_kernel(const float* __restrict__ xl,
                                  const float* __restrict__ xr, int ld,
                                  const float* __restrict__ bl,
                                  const float* __restrict__ br,
                                  const float* __restrict__ att,
                                  const float* __restrict__ bias,
                                  float* __restrict__ out) {
    int w = (blockIdx.x * blockDim.x + threadIdx.x) >> 5;
    int lane = threadIdx.x & 31;
    if (w >= NP) return;
    const int i = w;
    const int cbase = lane * 8;

    float xri[8], atv[8], blv[8];
    {
        float4 a0 = *reinterpret_cast<const float4*>(xr + (size_t)i * ld + cbase);
        float4 a1 = *reinterpret_cast<const float4*>(xr + (size_t)i * ld + cbase + 4);
        float4 r0 = *reinterpret_cast<const float4*>(br + cbase);
        float4 r1 = *reinterpret_cast<const float4*>(br + cbase + 4);
        xri[0]=a0.x+r0.x; xri[1]=a0.y+r0.y; xri[2]=a0.z+r0.z; xri[3]=a0.w+r0.w;
        xri[4]=a1.x+r1.x; xri[5]=a1.y+r1.y; xri[6]=a1.z+r1.z; xri[7]=a1.w+r1.w;
        float4 t0 = *reinterpret_cast<const float4*>(att + cbase);
        float4 t1 = *reinterpret_cast<const float4*>(att + cbase + 4);
        atv[0]=t0.x; atv[1]=t0.y; atv[2]=t0.z; atv[3]=t0.w;
        atv[4]=t1.x; atv[5]=t1.y; atv[6]=t1.z; atv[7]=t1.w;
        float4 l0 = *reinterpret_cast<const float4*>(bl + cbase);
        float4 l1 = *reinterpret_cast<const float4*>(bl + cbase + 4);
        blv[0]=l0.x; blv[1]=l0.y; blv[2]=l0.z; blv[3]=l0.w;
        blv[4]=l1.x; blv[5]=l1.y; blv[6]=l1.z; blv[7]=l1.w;
    }

    float m = -CUDART_INF_F;
    float s = 0.f;
    float acc[8];
#pragma unroll
    for (int k = 0; k < 8; k++) acc[k] = 0.f;

    const int beg = g_off[i];
    const int end = g_off[i + 1];

    int j = i;           // self loop first
    int ptr = beg;
    while (true) {
        float xlj[8];
        {
            float4 a0 = *reinterpret_cast<const float4*>(xl + (size_t)j * ld + cbase);
            float4 a1 = *reinterpret_cast<const float4*>(xl + (size_t)j * ld + cbase + 4);
            xlj[0]=a0.x+blv[0]; xlj[1]=a0.y+blv[1]; xlj[2]=a0.z+blv[2]; xlj[3]=a0.w+blv[3];
            xlj[4]=a1.x+blv[4]; xlj[5]=a1.y+blv[5]; xlj[6]=a1.z+blv[6]; xlj[7]=a1.w+blv[7];
        }
        float p = 0.f;
#pragma unroll
        for (int k = 0; k < 8; k++) {
            float t = xlj[k] + xri[k];
            t = (t > 0.f) ? t : NEG_SLOPE * t;
            p = fmaf(atv[k], t, p);
        }
        p += __shfl_xor_sync(0xffffffffu, p, 8, 16);
        p += __shfl_xor_sync(0xffffffffu, p, 4, 16);
        p += __shfl_xor_sync(0xffffffffu, p, 2, 16);
        p += __shfl_xor_sync(0xffffffffu, p, 1, 16);

        float e  = p;
        float nm = fmaxf(m, e);
        float sc = __expf(m - nm);
        float wgt = __expf(e - nm);
        s = s * sc + wgt;
#pragma unroll
        for (int k = 0; k < 8; k++) acc[k] = fmaf(acc[k], sc, wgt * xlj[k]);
        m = nm;

        if (ptr >= end) break;
        j = g_srcs[ptr++];
    }

    float inv = 1.f / s;
#pragma unroll
    for (int k = 0; k < 8; k++)
        out[(size_t)i * DOUT + cbase + k] = acc[k] * inv + bias[cbase + k];
}

// ---------------- LN + ELU + residual (warp per row) ------------------------
__device__ __forceinline__ void ln_elu_row(const float* __restrict__ in,
                                           const float* __restrict__ g,
                                           const float* __restrict__ b,
                                           int lane, float* v) {
    const int cbase = lane * 8;
    float4 a0 = *reinterpret_cast<const float4*>(in + cbase);
    float4 a1 = *reinterpret_cast<const float4*>(in + cbase + 4);
    v[0]=a0.x; v[1]=a0.y; v[2]=a0.z; v[3]=a0.w;
    v[4]=a1.x; v[5]=a1.y; v[6]=a1.z; v[7]=a1.w;
    float s = 0.f, s2 = 0.f;
#pragma unroll
    for (int k = 0; k < 8; k++) { s += v[k]; s2 = fmaf(v[k], v[k], s2); }
#pragma unroll
    for (int o = 16; o >= 1; o >>= 1) {
        s  += __shfl_xor_sync(0xffffffffu, s,  o);
        s2 += __shfl_xor_sync(0xffffffffu, s2, o);
    }
    float mu  = s * (1.f / 256.f);
    float var = s2 * (1.f / 256.f) - mu * mu;
    float rs  = rsqrtf(var + 1e-5f);
#pragma unroll
    for (int k = 0; k < 8; k++) {
        int c = cbase + k;
        float t = (v[k] - mu) * rs * g[c] + b[c];
        v[k] = (t > 0.f) ? t : expm1f(t);
    }
}

__global__ void post1_kernel(const float* __restrict__ gat,
                             const float* __restrict__ res, int ldres,
                             const float* __restrict__ resb,
                             const float* __restrict__ lng,
                             const float* __restrict__ lnb,
                             float* __restrict__ h1,
                             __nv_bfloat16* __restrict__ h1hi,
                             __nv_bfloat16* __restrict__ h1lo) {
    int w = (blockIdx.x * blockDim.x + threadIdx.x) >> 5;
    int lane = threadIdx.x & 31;
    if (w >= MPAD) return;
    const int cbase = lane * 8;
    if (w >= NP) {
#pragma unroll
        for (int k = 0; k < 8; k++) {
            size_t idx = (size_t)w * DOUT + cbase + k;
            h1hi[idx] = __float2bfloat16(0.f);
            h1lo[idx] = __float2bfloat16(0.f);
        }
        return;
    }
    float v[8];
    ln_elu_row(gat + (size_t)w * DOUT, lng, lnb, lane, v);
#pragma unroll
    for (int k = 0; k < 8; k++) {
        int c = cbase + k;
        size_t idx = (size_t)w * DOUT + c;
        float hv = v[k] + res[(size_t)w * ldres + c] + resb[c];
        h1[idx] = hv;
        __nv_bfloat16 hb, lb;
        split_bf16(hv, hb, lb);
        h1hi[idx] = hb;
        h1lo[idx] = lb;
    }
}

__global__ void post2_kernel(const float* __restrict__ gat,
                             const float* __restrict__ h1,
                             const float* __restrict__ lng,
                             const float* __restrict__ lnb,
                             float* __restrict__ out) {
    int w = (blockIdx.x * blockDim.x + threadIdx.x) >> 5;
    int lane = threadIdx.x & 31;
    if (w >= NP) return;
    float v[8];
    ln_elu_row(gat + (size_t)w * DOUT, lng, lnb, lane, v);
    const int cbase = lane * 8;
#pragma unroll
    for (int k = 0; k < 8; k++) {
        size_t idx = (size_t)w * DOUT + cbase + k;
        float h1v = h1[idx];
        float h2v = v[k] + h1v;
        out[idx] = fmaxf(h1v, h2v);
    }
}

// ---------------- launch -----------------------------------------------------
extern "C" void kernel_launch(void* const* d_in, const int* in_sizes, int n_in,
                              void* d_out, int out_size) {
    const float* x     = (const float*)d_in[0];
    const int*   ei    = (const int*)  d_in[1];
    const float* W1l   = (const float*)d_in[2];
    const float* b1l   = (const float*)d_in[3];
    const float* W1r   = (const float*)d_in[4];
    const float* b1r   = (const float*)d_in[5];
    const float* att1  = (const float*)d_in[6];
    const float* bias1 = (const float*)d_in[7];
    const float* W2l   = (const float*)d_in[8];
    const float* b2l   = (const float*)d_in[9];
    const float* W2r   = (const float*)d_in[10];
    const float* b2r   = (const float*)d_in[11];
    const float* att2  = (const float*)d_in[12];
    const float* bias2 = (const float*)d_in[13];
    const float* ln1g  = (const float*)d_in[14];
    const float* ln1b  = (const float*)d_in[15];
    const float* ln2g  = (const float*)d_in[16];
    const float* ln2b  = (const float*)d_in[17];
    const float* resW  = (const float*)d_in[18];
    const float* resb  = (const float*)d_in[19];
    float* out = (float*)d_out;

    const int* e_src = ei;
    const int* e_dst = ei + NE;

    __nv_bfloat16 *xhi, *xlo, *w1hi, *w1lo, *w2hi, *w2lo, *h1hi, *h1lo;
    float *y1, *y2, *h1, *gat;
    cudaGetSymbolAddress((void**)&xhi,  g_xhi);
    cudaGetSymbolAddress((void**)&xlo,  g_xlo);
    cudaGetSymbolAddress((void**)&w1hi, g_w1hi);
    cudaGetSymbolAddress((void**)&w1lo, g_w1lo);
    cudaGetSymbolAddress((void**)&w2hi, g_w2hi);
    cudaGetSymbolAddress((void**)&w2lo, g_w2lo);
    cudaGetSymbolAddress((void**)&h1hi, g_h1hi);
    cudaGetSymbolAddress((void**)&h1lo, g_h1lo);
    cudaGetSymbolAddress((void**)&y1,   g_y1);
    cudaGetSymbolAddress((void**)&y2,   g_y2);
    cudaGetSymbolAddress((void**)&h1,   g_h1);
    cudaGetSymbolAddress((void**)&gat,  g_gat);

    cudaFuncSetAttribute(gemm_bf16x3, cudaFuncAttributeMaxDynamicSharedMemorySize,
                         GEMM_SMEM_BYTES);

    // input conversions
    {
        size_t tot = (size_t)MPAD * DIN / 4;
        convert_x_kernel<<<(unsigned)((tot + 255) / 256), 256>>>(x);
    }
    pack_w1_kernel<<<(DIN * N1 / 4 + 255) / 256, 256>>>(W1l, W1r, resW);
    pack_w2_kernel<<<(DOUT * N2 / 4 + 255) / 256, 256>>>(W2l, W2r);

    // CSR build (independent of GEMM)
    zero_deg_kernel<<<(NP + 255) / 256, 256>>>();
    count_deg_kernel<<<(NE + 255) / 256, 256>>>(e_dst);
    build_offsets_kernel<<<1, 1024>>>();
    scatter_edges_kernel<<<(NE + 255) / 256, 256>>>(e_src, e_dst);

    // layer-1 fused GEMM: y1 = x @ [W1l|W1r|resW]
    dim3 g1(N1 / GBN, MPAD / GBM);
    gemm_bf16x3<<<g1, 256, GEMM_SMEM_BYTES>>>(xhi, xlo, w1hi, w1lo, y1, DIN, N1);

    // layer-1 attention + post
    int gatherBlocks = (NP * 32 + 255) / 256;
    int postBlocks   = (MPAD * 32 + 255) / 256;
    gat_gather_kernel<<<gatherBlocks, 256>>>(y1 + 0, y1 + 256, N1, b1l, b1r,
                                             att1, bias1, gat);
    post1_kernel<<<postBlocks, 256>>>(gat, y1 + 512, N1, resb, ln1g, ln1b,
                                      h1, h1hi, h1lo);

    // layer-2 fused GEMM: y2 = h1 @ [W2l|W2r]
    dim3 g2(N2 / GBN, MPAD / GBM);
    gemm_bf16x3<<<g2, 256, GEMM_SMEM_BYTES>>>(h1hi, h1lo, w2hi, w2lo, y2, DOUT, N2);

    // layer-2 attention + post + JK-max
    gat_gather_kernel<<<gatherBlocks, 256>>>(y2 + 0, y2 + 256, N2, b2l, b2r,
                                             att2, bias2, gat);
    post2_kernel<<<gatherBlocks, 256>>>(gat, h1, ln2g, ln2b, out);
}

// round 4
// speedup vs baseline: 2.3363x; 1.1501x over previous
#include <cuda_runtime.h>
#include <cuda_bf16.h>
#include <mma.h>
#include <math.h>
#include <math_constants.h>
#include <cstdint>

using namespace nvcuda;

#define NP    30000
#define MPAD  30080          // 235 * 128
#define DIN   1536
#define DOUT  256
#define NE    320000
#define NEG_SLOPE 0.2f
#define N1    768            // xl1 | xr1 | res
#define N2    512            // xl2 | xr2

// ---------------- scratch (device globals; no cudaMalloc allowed) -----------
__device__ __align__(256) __nv_bfloat16 g_xhi[(size_t)MPAD * DIN];
__device__ __align__(256) __nv_bfloat16 g_xlo[(size_t)MPAD * DIN];
__device__ __align__(256) __nv_bfloat16 g_w1hi[(size_t)DIN * N1];   // [K, N]
__device__ __align__(256) __nv_bfloat16 g_w1lo[(size_t)DIN * N1];
__device__ __align__(256) __nv_bfloat16 g_w2hi[(size_t)DOUT * N2];  // [K, N]
__device__ __align__(256) __nv_bfloat16 g_w2lo[(size_t)DOUT * N2];
__device__ __align__(256) float g_y1[(size_t)MPAD * N1];
__device__ __align__(256) float g_y2[(size_t)MPAD * N2];
__device__ __align__(256) float g_h1[(size_t)MPAD * DOUT];
__device__ __align__(256) __nv_bfloat16 g_h1hi[(size_t)MPAD * DOUT];
__device__ __align__(256) __nv_bfloat16 g_h1lo[(size_t)MPAD * DOUT];

__device__ int g_deg[NP];
__device__ int g_off[NP + 1];
__device__ int g_cur[NP];
__device__ int g_srcs[NE];

// ---------------- helpers ----------------------------------------------------
__device__ __forceinline__ void split_bf16(float v, __nv_bfloat16& h, __nv_bfloat16& l) {
    h = __float2bfloat16(v);
    l = __float2bfloat16(v - __bfloat162float(h));
}

__device__ __forceinline__ void cp16(void* dst, const void* src) {
    unsigned saddr = (unsigned)__cvta_generic_to_shared(dst);
    asm volatile("cp.async.cg.shared.global [%0], [%1], 16;\n" :: "r"(saddr), "l"(src));
}

// ---------------- input conversion kernels -----------------------------------
__global__ void convert_x_kernel(const float* __restrict__ x) {
    size_t i4 = (size_t)blockIdx.x * blockDim.x + threadIdx.x;
    const size_t tot = (size_t)MPAD * DIN / 4;
    if (i4 >= tot) return;
    size_t row = i4 / (DIN / 4);
    float4 v;
    if (row < NP) v = *reinterpret_cast<const float4*>(x + i4 * 4);
    else          v = make_float4(0.f, 0.f, 0.f, 0.f);
    __nv_bfloat16 h, l;
    size_t o = i4 * 4;
    split_bf16(v.x, h, l); g_xhi[o+0] = h; g_xlo[o+0] = l;
    split_bf16(v.y, h, l); g_xhi[o+1] = h; g_xlo[o+1] = l;
    split_bf16(v.z, h, l); g_xhi[o+2] = h; g_xlo[o+2] = l;
    split_bf16(v.w, h, l); g_xhi[o+3] = h; g_xlo[o+3] = l;
}

__global__ void pack_w1_kernel(const float* __restrict__ W1l,
                               const float* __restrict__ W1r,
                               const float* __restrict__ resW) {
    int i4 = blockIdx.x * blockDim.x + threadIdx.x;          // over DIN*N1/4
    if (i4 >= DIN * N1 / 4) return;
    int k = i4 / (N1 / 4);
    int c = (i4 % (N1 / 4)) * 4;
    const float* W = (c < 256) ? W1l : (c < 512 ? W1r : resW);
    int cc = c & 255;
    float4 v = *reinterpret_cast<const float4*>(W + (size_t)k * 256 + cc);
    size_t o = (size_t)k * N1 + c;
    __nv_bfloat16 h, l;
    split_bf16(v.x, h, l); g_w1hi[o+0] = h; g_w1lo[o+0] = l;
    split_bf16(v.y, h, l); g_w1hi[o+1] = h; g_w1lo[o+1] = l;
    split_bf16(v.z, h, l); g_w1hi[o+2] = h; g_w1lo[o+2] = l;
    split_bf16(v.w, h, l); g_w1hi[o+3] = h; g_w1lo[o+3] = l;
}

__global__ void pack_w2_kernel(const float* __restrict__ W2l,
                               const float* __restrict__ W2r) {
    int i4 = blockIdx.x * blockDim.x + threadIdx.x;          // over DOUT*N2/4
    if (i4 >= DOUT * N2 / 4) return;
    int k = i4 / (N2 / 4);
    int c = (i4 % (N2 / 4)) * 4;
    const float* W = (c < 256) ? W2l : W2r;
    int cc = c & 255;
    float4 v = *reinterpret_cast<const float4*>(W + (size_t)k * 256 + cc);
    size_t o = (size_t)k * N2 + c;
    __nv_bfloat16 h, l;
    split_bf16(v.x, h, l); g_w2hi[o+0] = h; g_w2lo[o+0] = l;
    split_bf16(v.y, h, l); g_w2hi[o+1] = h; g_w2lo[o+1] = l;
    split_bf16(v.z, h, l); g_w2hi[o+2] = h; g_w2lo[o+2] = l;
    split_bf16(v.w, h, l); g_w2hi[o+3] = h; g_w2lo[o+3] = l;
}

// ---------------- bf16x3 tensor-core GEMM (wmma / HMMA) ----------------------
// Y[M,N] = (Ahi+Alo)[M,K] @ (Bhi+Blo)[K,N], dropping lo*lo.
// CTA 128x256, BK=32, 8 warps (2M x 4N), warp tile 64x64, 3-stage cp.async.
#define GBM 128
#define GBN 256
#define GBK 32
#define LDA 40      // 32 + 8 pad (bf16)
#define LDB 264     // 256 + 8 pad
#define STG_A (128 * LDA)
#define STG_B (32 * LDB)
#define STAGE_ELEMS (2 * STG_A + 2 * STG_B)
#define NSTAGE 3
#define GEMM_SMEM_BYTES (NSTAGE * STAGE_ELEMS * 2)

__device__ __forceinline__ void gemm_load_stage(
    __nv_bfloat16* st,
    const __nv_bfloat16* __restrict__ Ahi, const __nv_bfloat16* __restrict__ Alo,
    const __nv_bfloat16* __restrict__ Bhi, const __nv_bfloat16* __restrict__ Blo,
    int bm, int bn, int k0, int K, int N, int tid)
{
    __nv_bfloat16* sAhi = st;
    __nv_bfloat16* sAlo = st + STG_A;
    __nv_bfloat16* sBhi = st + 2 * STG_A;
    __nv_bfloat16* sBlo = st + 2 * STG_A + STG_B;
    // A: 128x32, 512 16B-chunks per matrix; 2 per thread
#pragma unroll
    for (int c = 0; c < 2; c++) {
        int idx = tid + c * 256;
        int row = idx >> 2;
        int col = (idx & 3) * 8;
        size_t g = (size_t)(bm + row) * K + k0 + col;
        int s = row * LDA + col;
        cp16(sAhi + s, Ahi + g);
        cp16(sAlo + s, Alo + g);
    }
    // B: 32x256, 1024 chunks per matrix; 4 per thread
#pragma unroll
    for (int c = 0; c < 4; c++) {
        int idx = tid + c * 256;
        int row = idx >> 5;
        int col = (idx & 31) * 8;
        size_t g = (size_t)(k0 + row) * N + bn + col;
        int s = row * LDB + col;
        cp16(sBhi + s, Bhi + g);
        cp16(sBlo + s, Blo + g);
    }
    asm volatile("cp.async.commit_group;\n");
}

__global__ __launch_bounds__(256, 1)
void gemm_bf16x3(const __nv_bfloat16* __restrict__ Ahi,
                 const __nv_bfloat16* __restrict__ Alo,
                 const __nv_bfloat16* __restrict__ Bhi,
                 const __nv_bfloat16* __restrict__ Blo,
                 float* __restrict__ Y, int K, int N)
{
    extern __shared__ __nv_bfloat16 smem[];
    const int tid = threadIdx.x;
    const int bm = blockIdx.y * GBM;
    const int bn = blockIdx.x * GBN;
    const int warp = tid >> 5;
    const int wm = (warp >> 2) * 64;   // 0 or 64
    const int wn = (warp & 3) * 64;    // 0..192

    wmma::fragment<wmma::accumulator, 16, 16, 16, float> acc[4][4];
#pragma unroll
    for (int i = 0; i < 4; i++)
#pragma unroll
        for (int j = 0; j < 4; j++) wmma::fill_fragment(acc[i][j], 0.f);

    const int KT = K / GBK;
    gemm_load_stage(smem + 0 * STAGE_ELEMS, Ahi, Alo, Bhi, Blo, bm, bn, 0,   K, N, tid);
    gemm_load_stage(smem + 1 * STAGE_ELEMS, Ahi, Alo, Bhi, Blo, bm, bn, GBK, K, N, tid);

    for (int kt = 0; kt < KT; kt++) {
        if (kt + 1 < KT) asm volatile("cp.async.wait_group 1;\n" ::: "memory");
        else             asm volatile("cp.async.wait_group 0;\n" ::: "memory");
        __syncthreads();
        if (kt + 2 < KT)
            gemm_load_stage(smem + ((kt + 2) % NSTAGE) * STAGE_ELEMS,
                            Ahi, Alo, Bhi, Blo, bm, bn, (kt + 2) * GBK, K, N, tid);

        __nv_bfloat16* st = smem + (kt % NSTAGE) * STAGE_ELEMS;
        const __nv_bfloat16* sAhi = st;
        const __nv_bfloat16* sAlo = st + STG_A;
        const __nv_bfloat16* sBhi = st + 2 * STG_A;
        const __nv_bfloat16* sBlo = st + 2 * STG_A + STG_B;

#pragma unroll
        for (int ks = 0; ks < 2; ks++) {
            wmma::fragment<wmma::matrix_a, 16, 16, 16, __nv_bfloat16, wmma::row_major> fahi[4], falo[4];
#pragma unroll
            for (int i = 0; i < 4; i++) {
                wmma::load_matrix_sync(fahi[i], sAhi + (wm + i * 16) * LDA + ks * 16, LDA);
                wmma::load_matrix_sync(falo[i], sAlo + (wm + i * 16) * LDA + ks * 16, LDA);
            }
#pragma unroll
            for (int j = 0; j < 4; j++) {
                wmma::fragment<wmma::matrix_b, 16, 16, 16, __nv_bfloat16, wmma::row_major> fbhi, fblo;
                wmma::load_matrix_sync(fbhi, sBhi + ks * 16 * LDB + wn + j * 16, LDB);
                wmma::load_matrix_sync(fblo, sBlo + ks * 16 * LDB + wn + j * 16, LDB);
#pragma unroll
                for (int i = 0; i < 4; i++) {
                    wmma::mma_sync(acc[i][j], fahi[i], fbhi, acc[i][j]);
                    wmma::mma_sync(acc[i][j], falo[i], fbhi, acc[i][j]);
                    wmma::mma_sync(acc[i][j], fahi[i], fblo, acc[i][j]);
                }
            }
        }
        __syncthreads();
    }

#pragma unroll
    for (int i = 0; i < 4; i++)
#pragma unroll
        for (int j = 0; j < 4; j++)
            wmma::store_matrix_sync(Y + (size_t)(bm + wm + i * 16) * N + bn + wn + j * 16,
                                    acc[i][j], N, wmma::mem_row_major);
}

// ---------------- CSR build --------------------------------------------------
__global__ void zero_deg_kernel() {
    int i = blockIdx.x * blockDim.x + threadIdx.x;
    if (i < NP) g_deg[i] = 0;
}

__global__ void count_deg_kernel(const int* __restrict__ dst) {
    int e = blockIdx.x * blockDim.x + threadIdx.x;
    if (e < NE) atomicAdd(&g_deg[dst[e]], 1);
}

__global__ void build_offsets_kernel() {
    __shared__ int ssum[1024];
    const int tid = threadIdx.x;
    const int CHK = (NP + 1023) / 1024;
    int start = tid * CHK;
    int end = start + CHK; if (end > NP) end = NP;
    if (start > NP) start = NP;

    int s = 0;
    for (int i = start; i < end; i++) s += g_deg[i];
    ssum[tid] = s;
    __syncthreads();
    for (int o = 1; o < 1024; o <<= 1) {
        int v = (tid >= o) ? ssum[tid - o] : 0;
        __syncthreads();
        ssum[tid] += v;
        __syncthreads();
    }
    int run = (tid == 0) ? 0 : ssum[tid - 1];
    for (int i = start; i < end; i++) {
        g_off[i] = run;
        g_cur[i] = run;
        run += g_deg[i];
    }
    if (tid == 1023) g_off[NP] = ssum[1023];
}

__global__ void scatter_edges_kernel(const int* __restrict__ src,
                                     const int* __restrict__ dst) {
    int e = blockIdx.x * blockDim.x + threadIdx.x;
    if (e < NE) {
        int d = dst[e];
        int pos = atomicAdd(&g_cur[d], 1);
        g_srcs[pos] = src[e];
    }
}

// ---------------- fused GATv2 gather + softmax + LN/ELU epilogue -------------
// Warp per destination node; the warp ends up holding the full 256-ch row.
__device__ __forceinline__ void gat_core(const float* __restrict__ xl,
                                         const float* __restrict__ xr, int ld,
                                         const float* __restrict__ bl,
                                         const float* __restrict__ br,
                                         const float* __restrict__ att,
                                         const float* __restrict__ bias,
                                         int i, int lane, float* v /*out[8]*/) {
    const int cbase = lane * 8;
    float xri[8], atv[8], blv[8];
    {
        float4 a0 = *reinterpret_cast<const float4*>(xr + (size_t)i * ld + cbase);
        float4 a1 = *reinterpret_cast<const float4*>(xr + (size_t)i * ld + cbase + 4);
        float4 r0 = *reinterpret_cast<const float4*>(br + cbase);
        float4 r1 = *reinterpret_cast<const float4*>(br + cbase + 4);
        xri[0]=a0.x+r0.x; xri[1]=a0.y+r0.y; xri[2]=a0.z+r0.z; xri[3]=a0.w+r0.w;
        xri[4]=a1.x+r1.x; xri[5]=a1.y+r1.y; xri[6]=a1.z+r1.z; xri[7]=a1.w+r1.w;
        float4 t0 = *reinterpret_cast<const float4*>(att + cbase);
        float4 t1 = *reinterpret_cast<const float4*>(att + cbase + 4);
        atv[0]=t0.x; atv[1]=t0.y; atv[2]=t0.z; atv[3]=t0.w;
        atv[4]=t1.x; atv[5]=t1.y; atv[6]=t1.z; atv[7]=t1.w;
        float4 l0 = *reinterpret_cast<const float4*>(bl + cbase);
        float4 l1 = *reinterpret_cast<const float4*>(bl + cbase + 4);
        blv[0]=l0.x; blv[1]=l0.y; blv[2]=l0.z; blv[3]=l0.w;
        blv[4]=l1.x; blv[5]=l1.y; blv[6]=l1.z; blv[7]=l1.w;
    }

    float m = -CUDART_INF_F;
    float s = 0.f;
    float acc[8];
#pragma unroll
    for (int k = 0; k < 8; k++) acc[k] = 0.f;

    const int beg = g_off[i];
    const int end = g_off[i + 1];

    int j = i;           // self loop first
    int ptr = beg;
    while (true) {
        float xlj[8];
        {
            float4 a0 = *reinterpret_cast<const float4*>(xl + (size_t)j * ld + cbase);
            float4 a1 = *reinterpret_cast<const float4*>(xl + (size_t)j * ld + cbase + 4);
            xlj[0]=a0.x+blv[0]; xlj[1]=a0.y+blv[1]; xlj[2]=a0.z+blv[2]; xlj[3]=a0.w+blv[3];
            xlj[4]=a1.x+blv[4]; xlj[5]=a1.y+blv[5]; xlj[6]=a1.z+blv[6]; xlj[7]=a1.w+blv[7];
        }
        float p = 0.f;
#pragma unroll
        for (int k = 0; k < 8; k++) {
            float t = xlj[k] + xri[k];
            t = (t > 0.f) ? t : NEG_SLOPE * t;
            p = fmaf(atv[k], t, p);
        }
        p += __shfl_xor_sync(0xffffffffu, p, 8, 16);
        p += __shfl_xor_sync(0xffffffffu, p, 4, 16);
        p += __shfl_xor_sync(0xffffffffu, p, 2, 16);
        p += __shfl_xor_sync(0xffffffffu, p, 1, 16);

        float e  = p;
        float nm = fmaxf(m, e);
        float sc = __expf(m - nm);
        float wgt = __expf(e - nm);
        s = s * sc + wgt;
#pragma unroll
        for (int k = 0; k < 8; k++) acc[k] = fmaf(acc[k], sc, wgt * xlj[k]);
        m = nm;

        if (ptr >= end) break;
        j = g_srcs[ptr++];
    }

    float inv = 1.f / s;
#pragma unroll
    for (int k = 0; k < 8; k++)
        v[k] = acc[k] * inv + bias[lane * 8 + k];
}

__device__ __forceinline__ void ln_elu_inplace(float* v,
                                               const float* __restrict__ g,
                                               const float* __restrict__ b,
                                               int lane) {
    float s = 0.f, s2 = 0.f;
#pragma unroll
    for (int k = 0; k < 8; k++) { s += v[k]; s2 = fmaf(v[k], v[k], s2); }
#pragma unroll
    for (int o = 16; o >= 1; o >>= 1) {
        s  += __shfl_xor_sync(0xffffffffu, s,  o);
        s2 += __shfl_xor_sync(0xffffffffu, s2, o);
    }
    float mu  = s * (1.f / 256.f);
    float var = s2 * (1.f / 256.f) - mu * mu;
    float rs  = rsqrtf(var + 1e-5f);
#pragma unroll
    for (int k = 0; k < 8; k++) {
        int c = lane * 8 + k;
        float t = (v[k] - mu) * rs * g[c] + b[c];
        v[k] = (t > 0.f) ? t : expm1f(t);
    }
}

// layer 1: gather -> LN -> ELU -> + residual -> h1 (+ bf16 split)
__global__ void gat1_kernel(const float* __restrict__ y1,
                            const float* __restrict__ bl,
                            const float* __restrict__ br,
                            const float* __restrict__ att,
                            const float* __restrict__ bias,
                            const float* __restrict__ resb,
                            const float* __restrict__ lng,
                            const float* __restrict__ lnb,
                            float* __restrict__ h1,
                            __nv_bfloat16* __restrict__ h1hi,
                            __nv_bfloat16* __restrict__ h1lo) {
    int w = (blockIdx.x * blockDim.x + threadIdx.x) >> 5;
    int lane = threadIdx.x & 31;
    if (w >= NP) return;
    float v[8];
    gat_core(y1 + 0, y1 + 256, N1, bl, br, att, bias, w, lane, v);
    ln_elu_inplace(v, lng, lnb, lane);
    const int cbase = lane * 8;
    const float* res = y1 + 512;
#pragma unroll
    for (int k = 0; k < 8; k++) {
        int c = cbase + k;
        size_t idx = (size_t)w * DOUT + c;
        float hv = v[k] + res[(size_t)w * N1 + c] + resb[c];
        h1[idx] = hv;
        __nv_bfloat16 hb, lb;
        split_bf16(hv, hb, lb);
        h1hi[idx] = hb;
        h1lo[idx] = lb;
    }
}

// layer 2: gather -> LN -> ELU -> + h1 -> JK max
__global__ void gat2_kernel(const float* __restrict__ y2,
                            const float* __restrict__ bl,
                            const float* __restrict__ br,
                            const float* __restrict__ att,
                            const float* __restrict__ bias,
                            const float* __restrict__ lng,
                            const float* __restrict__ lnb,
                            const float* __restrict__ h1,
                            float* __restrict__ out) {
    int w = (blockIdx.x * blockDim.x + threadIdx.x) >> 5;
    int lane = threadIdx.x & 31;
    if (w >= NP) return;
    float v[8];
    gat_core(y2 + 0, y2 + 256, N2, bl, br, att, bias, w, lane, v);
    ln_elu_inplace(v, lng, lnb, lane);
    const int cbase = lane * 8;
#pragma unroll
    for (int k = 0; k < 8; k++) {
        size_t idx = (size_t)w * DOUT + cbase + k;
        float h1v = h1[idx];
        out[idx] = fmaxf(h1v, v[k] + h1v);
    }
}

// zero bf16 pad rows of h1hi/h1lo (rows NP..MPAD) so GEMM2 reads zeros
__global__ void pad_h1_kernel(__nv_bfloat16* __restrict__ h1hi,
                              __nv_bfloat16* __restrict__ h1lo) {
    int i = blockIdx.x * blockDim.x + threadIdx.x;
    int tot = (MPAD - NP) * DOUT;
    if (i >= tot) return;
    size_t idx = (size_t)NP * DOUT + i;
    h1hi[idx] = __float2bfloat16(0.f);
    h1lo[idx] = __float2bfloat16(0.f);
}

// ---------------- launch -----------------------------------------------------
extern "C" void kernel_launch(void* const* d_in, const int* in_sizes, int n_in,
                              void* d_out, int out_size) {
    const float* x     = (const float*)d_in[0];
    const int*   ei    = (const int*)  d_in[1];
    const float* W1l   = (const float*)d_in[2];
    const float* b1l   = (const float*)d_in[3];
    const float* W1r   = (const float*)d_in[4];
    const float* b1r   = (const float*)d_in[5];
    const float* att1  = (const float*)d_in[6];
    const float* bias1 = (const float*)d_in[7];
    const float* W2l   = (const float*)d_in[8];
    const float* b2l   = (const float*)d_in[9];
    const float* W2r   = (const float*)d_in[10];
    const float* b2r   = (const float*)d_in[11];
    const float* att2  = (const float*)d_in[12];
    const float* bias2 = (const float*)d_in[13];
    const float* ln1g  = (const float*)d_in[14];
    const float* ln1b  = (const float*)d_in[15];
    const float* ln2g  = (const float*)d_in[16];
    const float* ln2b  = (const float*)d_in[17];
    const float* resW  = (const float*)d_in[18];
    const float* resb  = (const float*)d_in[19];
    float* out = (float*)d_out;

    const int* e_src = ei;
    const int* e_dst = ei + NE;

    __nv_bfloat16 *xhi, *xlo, *w1hi, *w1lo, *w2hi, *w2lo, *h1hi, *h1lo;
    float *y1, *y2, *h1;
    cudaGetSymbolAddress((void**)&xhi,  g_xhi);
    cudaGetSymbolAddress((void**)&xlo,  g_xlo);
    cudaGetSymbolAddress((void**)&w1hi, g_w1hi);
    cudaGetSymbolAddress((void**)&w1lo, g_w1lo);
    cudaGetSymbolAddress((void**)&w2hi, g_w2hi);
    cudaGetSymbolAddress((void**)&w2lo, g_w2lo);
    cudaGetSymbolAddress((void**)&h1hi, g_h1hi);
    cudaGetSymbolAddress((void**)&h1lo, g_h1lo);
    cudaGetSymbolAddress((void**)&y1,   g_y1);
    cudaGetSymbolAddress((void**)&y2,   g_y2);
    cudaGetSymbolAddress((void**)&h1,   g_h1);

    cudaFuncSetAttribute(gemm_bf16x3, cudaFuncAttributeMaxDynamicSharedMemorySize,
                         GEMM_SMEM_BYTES);

    // input conversions
    {
        size_t tot = (size_t)MPAD * DIN / 4;
        convert_x_kernel<<<(unsigned)((tot + 255) / 256), 256>>>(x);
    }
    pack_w1_kernel<<<(DIN * N1 / 4 + 255) / 256, 256>>>(W1l, W1r, resW);
    pack_w2_kernel<<<(DOUT * N2 / 4 + 255) / 256, 256>>>(W2l, W2r);

    // CSR build
    zero_deg_kernel<<<(NP + 255) / 256, 256>>>();
    count_deg_kernel<<<(NE + 255) / 256, 256>>>(e_dst);
    build_offsets_kernel<<<1, 1024>>>();
    scatter_edges_kernel<<<(NE + 255) / 256, 256>>>(e_src, e_dst);

    // layer-1 fused GEMM: y1 = x @ [W1l|W1r|resW]
    gemm_bf16x3<<<dim3(N1 / GBN, MPAD / GBM), 256, GEMM_SMEM_BYTES>>>(
        xhi, xlo, w1hi, w1lo, y1, DIN, N1);

    // layer-1 gather + LN/ELU/residual (fused)
    int gatherBlocks = (NP * 32 + 255) / 256;
    gat1_kernel<<<gatherBlocks, 256>>>(y1, b1l, b1r, att1, bias1, resb,
                                       ln1g, ln1b, h1, h1hi, h1lo);
    pad_h1_kernel<<<((MPAD - NP) * DOUT + 255) / 256, 256>>>(h1hi, h1lo);

    // layer-2 fused GEMM: y2 = h1 @ [W2l|W2r]
    gemm_bf16x3<<<dim3(N2 / GBN, MPAD / GBM), 256, GEMM_SMEM_BYTES>>>(
        h1hi, h1lo, w2hi, w2lo, y2, DOUT, N2);

    // layer-2 gather + LN/ELU + JK-max (fused)
    gat2_kernel<<<gatherBlocks, 256>>>(y2, b2l, b2r, att2, bias2,
                                       ln2g, ln2b, h1, out);
}

// round 5
// speedup vs baseline: 3.2474x; 1.3900x over previous
#include <cuda_runtime.h>
#include <cuda_fp16.h>
#include <mma.h>
#include <math.h>
#include <math_constants.h>
#include <cstdint>

using namespace nvcuda;

#define NP    30000
#define MPAD  30080          // 235 * 128
#define DIN   1536
#define DOUT  256
#define NE    320000
#define NEG_SLOPE 0.2f
#define N1    768            // xl1 | xr1 | res
#define N2    512            // xl2 | xr2

// ---------------- scratch (device globals; no cudaMalloc allowed) -----------
__device__ __align__(256) __half g_xhi[(size_t)MPAD * DIN];
__device__ __align__(256) __half g_xlo[(size_t)MPAD * DIN];
__device__ __align__(256) __half g_w1[(size_t)DIN * N1];    // [K, N] fp16
__device__ __align__(256) __half g_w2[(size_t)DOUT * N2];   // [K, N] fp16
__device__ __align__(256) float g_y1[(size_t)MPAD * N1];
__device__ __align__(256) float g_y2[(size_t)MPAD * N2];
__device__ __align__(256) float g_h1[(size_t)MPAD * DOUT];
__device__ __align__(256) __half g_h1hi[(size_t)MPAD * DOUT];
__device__ __align__(256) __half g_h1lo[(size_t)MPAD * DOUT];

__device__ int g_deg[NP];
__device__ int g_off[NP + 1];
__device__ int g_cur[NP];
__device__ int g_srcs[NE];

// ---------------- helpers ----------------------------------------------------
__device__ __forceinline__ void split_h16(float v, __half& h, __half& l) {
    h = __float2half_rn(v);
    l = __float2half_rn(v - __half2float(h));
}

__device__ __forceinline__ void cp16(void* dst, const void* src) {
    unsigned saddr = (unsigned)__cvta_generic_to_shared(dst);
    asm volatile("cp.async.cg.shared.global [%0], [%1], 16;\n" :: "r"(saddr), "l"(src));
}

// ---------------- input conversion kernels -----------------------------------
__global__ void convert_x_kernel(const float* __restrict__ x) {
    size_t i4 = (size_t)blockIdx.x * blockDim.x + threadIdx.x;
    const size_t tot = (size_t)MPAD * DIN / 4;
    if (i4 >= tot) return;
    size_t row = i4 / (DIN / 4);
    float4 v;
    if (row < NP) v = *reinterpret_cast<const float4*>(x + i4 * 4);
    else          v = make_float4(0.f, 0.f, 0.f, 0.f);
    __half h, l;
    size_t o = i4 * 4;
    split_h16(v.x, h, l); g_xhi[o+0] = h; g_xlo[o+0] = l;
    split_h16(v.y, h, l); g_xhi[o+1] = h; g_xlo[o+1] = l;
    split_h16(v.z, h, l); g_xhi[o+2] = h; g_xlo[o+2] = l;
    split_h16(v.w, h, l); g_xhi[o+3] = h; g_xlo[o+3] = l;
}

__global__ void pack_w1_kernel(const float* __restrict__ W1l,
                               const float* __restrict__ W1r,
                               const float* __restrict__ resW) {
    int i4 = blockIdx.x * blockDim.x + threadIdx.x;          // over DIN*N1/4
    if (i4 >= DIN * N1 / 4) return;
    int k = i4 / (N1 / 4);
    int c = (i4 % (N1 / 4)) * 4;
    const float* W = (c < 256) ? W1l : (c < 512 ? W1r : resW);
    int cc = c & 255;
    float4 v = *reinterpret_cast<const float4*>(W + (size_t)k * 256 + cc);
    size_t o = (size_t)k * N1 + c;
    g_w1[o+0] = __float2half_rn(v.x);
    g_w1[o+1] = __float2half_rn(v.y);
    g_w1[o+2] = __float2half_rn(v.z);
    g_w1[o+3] = __float2half_rn(v.w);
}

__global__ void pack_w2_kernel(const float* __restrict__ W2l,
                               const float* __restrict__ W2r) {
    int i4 = blockIdx.x * blockDim.x + threadIdx.x;          // over DOUT*N2/4
    if (i4 >= DOUT * N2 / 4) return;
    int k = i4 / (N2 / 4);
    int c = (i4 % (N2 / 4)) * 4;
    const float* W = (c < 256) ? W2l : W2r;
    int cc = c & 255;
    float4 v = *reinterpret_cast<const float4*>(W + (size_t)k * 256 + cc);
    size_t o = (size_t)k * N2 + c;
    g_w2[o+0] = __float2half_rn(v.x);
    g_w2[o+1] = __float2half_rn(v.y);
    g_w2[o+2] = __float2half_rn(v.z);
    g_w2[o+3] = __float2half_rn(v.w);
}

// ---------------- fp16 A-split tensor-core GEMM ------------------------------
// Y[M,N] = (Ahi+Alo)[M,K] @ B[K,N]; A split keeps x/h1 at ~fp32 precision,
// B single fp16 (error ~2.8e-4 rel rms, dominates; within 1e-3 gate).
// CTA 128x256, BK=32, 8 warps (2M x 4N), warp tile 64x64, 3-stage cp.async.
#define GBM 128
#define GBN 256
#define GBK 32
#define LDA 40      // 32 + 8 pad (halfs)
#define LDB 264     // 256 + 8 pad
#define STG_A (128 * LDA)
#define STG_B (32 * LDB)
#define STAGE_ELEMS (2 * STG_A + STG_B)
#define NSTAGE 3
#define GEMM_SMEM_BYTES (NSTAGE * STAGE_ELEMS * 2)

__device__ __forceinline__ void gemm_load_stage(
    __half* st,
    const __half* __restrict__ Ahi, const __half* __restrict__ Alo,
    const __half* __restrict__ B,
    int bm, int bn, int k0, int K, int N, int tid)
{
    __half* sAhi = st;
    __half* sAlo = st + STG_A;
    __half* sB   = st + 2 * STG_A;
    // A: 128x32 halfs = 512 x 16B chunks per matrix; 2 per thread each
#pragma unroll
    for (int c = 0; c < 2; c++) {
        int idx = tid + c * 256;
        int row = idx >> 2;
        int col = (idx & 3) * 8;
        size_t g = (size_t)(bm + row) * K + k0 + col;
        int s = row * LDA + col;
        cp16(sAhi + s, Ahi + g);
        cp16(sAlo + s, Alo + g);
    }
    // B: 32x256 halfs = 1024 chunks; 4 per thread
#pragma unroll
    for (int c = 0; c < 4; c++) {
        int idx = tid + c * 256;
        int row = idx >> 5;
        int col = (idx & 31) * 8;
        size_t g = (size_t)(k0 + row) * N + bn + col;
        int s = row * LDB + col;
        cp16(sB + s, B + g);
    }
    asm volatile("cp.async.commit_group;\n");
}

__global__ __launch_bounds__(256, 1)
void gemm_h16x2(const __half* __restrict__ Ahi,
                const __half* __restrict__ Alo,
                const __half* __restrict__ B,
                float* __restrict__ Y, int K, int N)
{
    extern __shared__ __half smem[];
    const int tid = threadIdx.x;
    const int bm = blockIdx.y * GBM;
    const int bn = blockIdx.x * GBN;
    const int warp = tid >> 5;
    const int wm = (warp >> 2) * 64;   // 0 or 64
    const int wn = (warp & 3) * 64;    // 0..192

    wmma::fragment<wmma::accumulator, 16, 16, 16, float> acc[4][4];
#pragma unroll
    for (int i = 0; i < 4; i++)
#pragma unroll
        for (int j = 0; j < 4; j++) wmma::fill_fragment(acc[i][j], 0.f);

    const int KT = K / GBK;
    gemm_load_stage(smem + 0 * STAGE_ELEMS, Ahi, Alo, B, bm, bn, 0,   K, N, tid);
    gemm_load_stage(smem + 1 * STAGE_ELEMS, Ahi, Alo, B, bm, bn, GBK, K, N, tid);

    for (int kt = 0; kt < KT; kt++) {
        if (kt + 1 < KT) asm volatile("cp.async.wait_group 1;\n" ::: "memory");
        else             asm volatile("cp.async.wait_group 0;\n" ::: "memory");
        // single sync: proves every warp finished compute(kt-1), so the stage
        // prefetch(kt+2) overwrites ((kt+2)%3 == (kt-1)%3) is free.
        __syncthreads();
        if (kt + 2 < KT)
            gemm_load_stage(smem + ((kt + 2) % NSTAGE) * STAGE_ELEMS,
                            Ahi, Alo, B, bm, bn, (kt + 2) * GBK, K, N, tid);

        __half* st = smem + (kt % NSTAGE) * STAGE_ELEMS;
        const __half* sAhi = st;
        const __half* sAlo = st + STG_A;
        const __half* sB   = st + 2 * STG_A;

#pragma unroll
        for (int ks = 0; ks < 2; ks++) {
            wmma::fragment<wmma::matrix_a, 16, 16, 16, __half, wmma::row_major> fahi[4], falo[4];
#pragma unroll
            for (int i = 0; i < 4; i++) {
                wmma::load_matrix_sync(fahi[i], sAhi + (wm + i * 16) * LDA + ks * 16, LDA);
                wmma::load_matrix_sync(falo[i], sAlo + (wm + i * 16) * LDA + ks * 16, LDA);
            }
#pragma unroll
            for (int j = 0; j < 4; j++) {
                wmma::fragment<wmma::matrix_b, 16, 16, 16, __half, wmma::row_major> fb;
                wmma::load_matrix_sync(fb, sB + ks * 16 * LDB + wn + j * 16, LDB);
#pragma unroll
                for (int i = 0; i < 4; i++) {
                    wmma::mma_sync(acc[i][j], fahi[i], fb, acc[i][j]);
                    wmma::mma_sync(acc[i][j], falo[i], fb, acc[i][j]);
                }
            }
        }
    }

#pragma unroll
    for (int i = 0; i < 4; i++)
#pragma unroll
        for (int j = 0; j < 4; j++)
            wmma::store_matrix_sync(Y + (size_t)(bm + wm + i * 16) * N + bn + wn + j * 16,
                                    acc[i][j], N, wmma::mem_row_major);
}

// ---------------- CSR build --------------------------------------------------
__global__ void zero_deg_kernel() {
    int i = blockIdx.x * blockDim.x + threadIdx.x;
    if (i < NP) g_deg[i] = 0;
}

__global__ void count_deg_kernel(const int* __restrict__ dst) {
    int e = blockIdx.x * blockDim.x + threadIdx.x;
    if (e < NE) atomicAdd(&g_deg[dst[e]], 1);
}

__global__ void build_offsets_kernel() {
    __shared__ int ssum[1024];
    const int tid = threadIdx.x;
    const int CHK = (NP + 1023) / 1024;
    int start = tid * CHK;
    int end = start + CHK; if (end > NP) end = NP;
    if (start > NP) start = NP;

    int s = 0;
    for (int i = start; i < end; i++) s += g_deg[i];
    ssum[tid] = s;
    __syncthreads();
    for (int o = 1; o < 1024; o <<= 1) {
        int v = (tid >= o) ? ssum[tid - o] : 0;
        __syncthreads();
        ssum[tid] += v;
        __syncthreads();
    }
    int run = (tid == 0) ? 0 : ssum[tid - 1];
    for (int i = start; i < end; i++) {
        g_off[i] = run;
        g_cur[i] = run;
        run += g_deg[i];
    }
    if (tid == 1023) g_off[NP] = ssum[1023];
}

__global__ void scatter_edges_kernel(const int* __restrict__ src,
                                     const int* __restrict__ dst) {
    int e = blockIdx.x * blockDim.x + threadIdx.x;
    if (e < NE) {
        int d = dst[e];
        int pos = atomicAdd(&g_cur[d], 1);
        g_srcs[pos] = src[e];
    }
}

// ---------------- fused GATv2 gather + softmax + LN/ELU epilogue -------------
__device__ __forceinline__ void gat_core(const float* __restrict__ xl,
                                         const float* __restrict__ xr, int ld,
                                         const float* __restrict__ bl,
                                         const float* __restrict__ br,
                                         const float* __restrict__ att,
                                         const float* __restrict__ bias,
                                         int i, int lane, float* v /*out[8]*/) {
    const int cbase = lane * 8;
    float xri[8], atv[8], blv[8];
    {
        float4 a0 = *reinterpret_cast<const float4*>(xr + (size_t)i * ld + cbase);
        float4 a1 = *reinterpret_cast<const float4*>(xr + (size_t)i * ld + cbase + 4);
        float4 r0 = *reinterpret_cast<const float4*>(br + cbase);
        float4 r1 = *reinterpret_cast<const float4*>(br + cbase + 4);
        xri[0]=a0.x+r0.x; xri[1]=a0.y+r0.y; xri[2]=a0.z+r0.z; xri[3]=a0.w+r0.w;
        xri[4]=a1.x+r1.x; xri[5]=a1.y+r1.y; xri[6]=a1.z+r1.z; xri[7]=a1.w+r1.w;
        float4 t0 = *reinterpret_cast<const float4*>(att + cbase);
        float4 t1 = *reinterpret_cast<const float4*>(att + cbase + 4);
        atv[0]=t0.x; atv[1]=t0.y; atv[2]=t0.z; atv[3]=t0.w;
        atv[4]=t1.x; atv[5]=t1.y; atv[6]=t1.z; atv[7]=t1.w;
        float4 l0 = *reinterpret_cast<const float4*>(bl + cbase);
        float4 l1 = *reinterpret_cast<const float4*>(bl + cbase + 4);
        blv[0]=l0.x; blv[1]=l0.y; blv[2]=l0.z; blv[3]=l0.w;
        blv[4]=l1.x; blv[5]=l1.y; blv[6]=l1.z; blv[7]=l1.w;
    }

    float m = -CUDART_INF_F;
    float s = 0.f;
    float acc[8];
#pragma unroll
    for (int k = 0; k < 8; k++) acc[k] = 0.f;

    const int beg = g_off[i];
    const int end = g_off[i + 1];

    int j = i;           // self loop first
    int ptr = beg;
    while (true) {
        float xlj[8];
        {
            float4 a0 = *reinterpret_cast<const float4*>(xl + (size_t)j * ld + cbase);
            float4 a1 = *reinterpret_cast<const float4*>(xl + (size_t)j * ld + cbase + 4);
            xlj[0]=a0.x+blv[0]; xlj[1]=a0.y+blv[1]; xlj[2]=a0.z+blv[2]; xlj[3]=a0.w+blv[3];
            xlj[4]=a1.x+blv[4]; xlj[5]=a1.y+blv[5]; xlj[6]=a1.z+blv[6]; xlj[7]=a1.w+blv[7];
        }
        float p = 0.f;
#pragma unroll
        for (int k = 0; k < 8; k++) {
            float t = xlj[k] + xri[k];
            t = (t > 0.f) ? t : NEG_SLOPE * t;
            p = fmaf(atv[k], t, p);
        }
        p += __shfl_xor_sync(0xffffffffu, p, 8, 16);
        p += __shfl_xor_sync(0xffffffffu, p, 4, 16);
        p += __shfl_xor_sync(0xffffffffu, p, 2, 16);
        p += __shfl_xor_sync(0xffffffffu, p, 1, 16);

        float e  = p;
        float nm = fmaxf(m, e);
        float sc = __expf(m - nm);
        float wgt = __expf(e - nm);
        s = s * sc + wgt;
#pragma unroll
        for (int k = 0; k < 8; k++) acc[k] = fmaf(acc[k], sc, wgt * xlj[k]);
        m = nm;

        if (ptr >= end) break;
        j = g_srcs[ptr++];
    }

    float inv = 1.f / s;
#pragma unroll
    for (int k = 0; k < 8; k++)
        v[k] = acc[k] * inv + bias[lane * 8 + k];
}

__device__ __forceinline__ void ln_elu_inplace(float* v,
                                               const float* __restrict__ g,
                                               const float* __restrict__ b,
                                               int lane) {
    float s = 0.f, s2 = 0.f;
#pragma unroll
    for (int k = 0; k < 8; k++) { s += v[k]; s2 = fmaf(v[k], v[k], s2); }
#pragma unroll
    for (int o = 16; o >= 1; o >>= 1) {
        s  += __shfl_xor_sync(0xffffffffu, s,  o);
        s2 += __shfl_xor_sync(0xffffffffu, s2, o);
    }
    float mu  = s * (1.f / 256.f);
    float var = s2 * (1.f / 256.f) - mu * mu;
    float rs  = rsqrtf(var + 1e-5f);
#pragma unroll
    for (int k = 0; k < 8; k++) {
        int c = lane * 8 + k;
        float t = (v[k] - mu) * rs * g[c] + b[c];
        v[k] = (t > 0.f) ? t : expm1f(t);
    }
}

// layer 1: gather -> LN -> ELU -> + residual -> h1 (+ fp16 split); pad rows zeroed
__global__ void gat1_kernel(const float* __restrict__ y1,
                            const float* __restrict__ bl,
                            const float* __restrict__ br,
                            const float* __restrict__ att,
                            const float* __restrict__ bias,
                            const float* __restrict__ resb,
                            const float* __restrict__ lng,
                            const float* __restrict__ lnb,
                            float* __restrict__ h1,
                            __half* __restrict__ h1hi,
                            __half* __restrict__ h1lo) {
    int w = (blockIdx.x * blockDim.x + threadIdx.x) >> 5;
    int lane = threadIdx.x & 31;
    if (w >= MPAD) return;
    const int cbase = lane * 8;
    if (w >= NP) {      // zero the GEMM2 pad rows
#pragma unroll
        for (int k = 0; k < 8; k++) {
            size_t idx = (size_t)w * DOUT + cbase + k;
            h1hi[idx] = __float2half_rn(0.f);
            h1lo[idx] = __float2half_rn(0.f);
        }
        return;
    }
    float v[8];
    gat_core(y1 + 0, y1 + 256, N1, bl, br, att, bias, w, lane, v);
    ln_elu_inplace(v, lng, lnb, lane);
    const float* res = y1 + 512;
#pragma unroll
    for (int k = 0; k < 8; k++) {
        int c = cbase + k;
        size_t idx = (size_t)w * DOUT + c;
        float hv = v[k] + res[(size_t)w * N1 + c] + resb[c];
        h1[idx] = hv;
        __half hb, lb;
        split_h16(hv, hb, lb);
        h1hi[idx] = hb;
        h1lo[idx] = lb;
    }
}

// layer 2: gather -> LN -> ELU -> + h1 -> JK max
__global__ void gat2_kernel(const float* __restrict__ y2,
                            const float* __restrict__ bl,
                            const float* __restrict__ br,
                            const float* __restrict__ att,
                            const float* __restrict__ bias,
                            const float* __restrict__ lng,
                            const float* __restrict__ lnb,
                            const float* __restrict__ h1,
                            float* __restrict__ out) {
    int w = (blockIdx.x * blockDim.x + threadIdx.x) >> 5;
    int lane = threadIdx.x & 31;
    if (w >= NP) return;
    float v[8];
    gat_core(y2 + 0, y2 + 256, N2, bl, br, att, bias, w, lane, v);
    ln_elu_inplace(v, lng, lnb, lane);
    const int cbase = lane * 8;
#pragma unroll
    for (int k = 0; k < 8; k++) {
        size_t idx = (size_t)w * DOUT + cbase + k;
        float h1v = h1[idx];
        out[idx] = fmaxf(h1v, v[k] + h1v);
    }
}

// ---------------- launch -----------------------------------------------------
extern "C" void kernel_launch(void* const* d_in, const int* in_sizes, int n_in,
                              void* d_out, int out_size) {
    const float* x     = (const float*)d_in[0];
    const int*   ei    = (const int*)  d_in[1];
    const float* W1l   = (const float*)d_in[2];
    const float* b1l   = (const float*)d_in[3];
    const float* W1r   = (const float*)d_in[4];
    const float* b1r   = (const float*)d_in[5];
    const float* att1  = (const float*)d_in[6];
    const float* bias1 = (const float*)d_in[7];
    const float* W2l   = (const float*)d_in[8];
    const float* b2l   = (const float*)d_in[9];
    const float* W2r   = (const float*)d_in[10];
    const float* b2r   = (const float*)d_in[11];
    const float* att2  = (const float*)d_in[12];
    const float* bias2 = (const float*)d_in[13];
    const float* ln1g  = (const float*)d_in[14];
    const float* ln1b  = (const float*)d_in[15];
    const float* ln2g  = (const float*)d_in[16];
    const float* ln2b  = (const float*)d_in[17];
    const float* resW  = (const float*)d_in[18];
    const float* resb  = (const float*)d_in[19];
    float* out = (float*)d_out;

    const int* e_src = ei;
    const int* e_dst = ei + NE;

    __half *xhi, *xlo, *w1, *w2, *h1hi, *h1lo;
    float *y1, *y2, *h1;
    cudaGetSymbolAddress((void**)&xhi,  g_xhi);
    cudaGetSymbolAddress((void**)&xlo,  g_xlo);
    cudaGetSymbolAddress((void**)&w1,   g_w1);
    cudaGetSymbolAddress((void**)&w2,   g_w2);
    cudaGetSymbolAddress((void**)&h1hi, g_h1hi);
    cudaGetSymbolAddress((void**)&h1lo, g_h1lo);
    cudaGetSymbolAddress((void**)&y1,   g_y1);
    cudaGetSymbolAddress((void**)&y2,   g_y2);
    cudaGetSymbolAddress((void**)&h1,   g_h1);

    cudaFuncSetAttribute(gemm_h16x2, cudaFuncAttributeMaxDynamicSharedMemorySize,
                         GEMM_SMEM_BYTES);

    // input conversions
    {
        size_t tot = (size_t)MPAD * DIN / 4;
        convert_x_kernel<<<(unsigned)((tot + 255) / 256), 256>>>(x);
    }
    pack_w1_kernel<<<(DIN * N1 / 4 + 255) / 256, 256>>>(W1l, W1r, resW);
    pack_w2_kernel<<<(DOUT * N2 / 4 + 255) / 256, 256>>>(W2l, W2r);

    // CSR build
    zero_deg_kernel<<<(NP + 255) / 256, 256>>>();
    count_deg_kernel<<<(NE + 255) / 256, 256>>>(e_dst);
    build_offsets_kernel<<<1, 1024>>>();
    scatter_edges_kernel<<<(NE + 255) / 256, 256>>>(e_src, e_dst);

    // layer-1 fused GEMM: y1 = x @ [W1l|W1r|resW]
    gemm_h16x2<<<dim3(N1 / GBN, MPAD / GBM), 256, GEMM_SMEM_BYTES>>>(
        xhi, xlo, w1, y1, DIN, N1);

    // layer-1 gather + LN/ELU/residual (fused; also zeroes pad rows)
    int gather1Blocks = (MPAD * 32 + 255) / 256;
    int gather2Blocks = (NP * 32 + 255) / 256;
    gat1_kernel<<<gather1Blocks, 256>>>(y1, b1l, b1r, att1, bias1, resb,
                                        ln1g, ln1b, h1, h1hi, h1lo);

    // layer-2 fused GEMM: y2 = h1 @ [W2l|W2r]
    gemm_h16x2<<<dim3(N2 / GBN, MPAD / GBM), 256, GEMM_SMEM_BYTES>>>(
        h1hi, h1lo, w2, y2, DOUT, N2);

    // layer-2 gather + LN/ELU + JK-max (fused)
    gat2_kernel<<<gather2Blocks, 256>>>(y2, b2l, b2r, att2, bias2,
                                        ln2g, ln2b, h1, out);
}

// round 6
// speedup vs baseline: 4.3572x; 1.3417x over previous
#include <cuda_runtime.h>
#include <cuda_fp16.h>
#include <mma.h>
#include <math.h>
#include <math_constants.h>
#include <cstdint>

using namespace nvcuda;

#define NP    30000
#define MPAD  30080          // 235 * 128
#define DIN   1536
#define DOUT  256
#define NE    320000
#define NEG_SLOPE 0.2f
#define N1    768            // xl1 | xr1 | res
#define N2    512            // xl2 | xr2

// ---------------- scratch (device globals; no cudaMalloc allowed) -----------
__device__ __align__(256) __half g_x16[(size_t)MPAD * DIN];
__device__ __align__(256) __half g_w1[(size_t)DIN * N1];    // [K, N] fp16
__device__ __align__(256) __half g_w2[(size_t)DOUT * N2];   // [K, N] fp16
__device__ __align__(256) float g_y1[(size_t)MPAD * N1];
__device__ __align__(256) float g_y2[(size_t)MPAD * N2];
__device__ __align__(256) float g_h1[(size_t)MPAD * DOUT];
__device__ __align__(256) __half g_h116[(size_t)MPAD * DOUT];

__device__ int g_deg[NP];
__device__ int g_off[NP + 1];
__device__ int g_cur[NP];
__device__ int g_srcs[NE];

// ---------------- helpers ----------------------------------------------------
__device__ __forceinline__ void cp16(void* dst, const void* src) {
    unsigned saddr = (unsigned)__cvta_generic_to_shared(dst);
    asm volatile("cp.async.cg.shared.global [%0], [%1], 16;\n" :: "r"(saddr), "l"(src));
}

// ---------------- input conversion kernels -----------------------------------
__global__ void convert_x_kernel(const float* __restrict__ x) {
    size_t i4 = (size_t)blockIdx.x * blockDim.x + threadIdx.x;
    const size_t tot = (size_t)MPAD * DIN / 4;
    if (i4 >= tot) return;
    size_t row = i4 / (DIN / 4);
    float4 v;
    if (row < NP) v = *reinterpret_cast<const float4*>(x + i4 * 4);
    else          v = make_float4(0.f, 0.f, 0.f, 0.f);
    __half2 h0 = make_half2(__float2half_rn(v.x), __float2half_rn(v.y));
    __half2 h1 = make_half2(__float2half_rn(v.z), __float2half_rn(v.w));
    *reinterpret_cast<__half2*>(g_x16 + i4 * 4)     = h0;
    *reinterpret_cast<__half2*>(g_x16 + i4 * 4 + 2) = h1;
}

__global__ void pack_w1_kernel(const float* __restrict__ W1l,
                               const float* __restrict__ W1r,
                               const float* __restrict__ resW) {
    int i4 = blockIdx.x * blockDim.x + threadIdx.x;          // over DIN*N1/4
    if (i4 >= DIN * N1 / 4) return;
    int k = i4 / (N1 / 4);
    int c = (i4 % (N1 / 4)) * 4;
    const float* W = (c < 256) ? W1l : (c < 512 ? W1r : resW);
    int cc = c & 255;
    float4 v = *reinterpret_cast<const float4*>(W + (size_t)k * 256 + cc);
    size_t o = (size_t)k * N1 + c;
    g_w1[o+0] = __float2half_rn(v.x);
    g_w1[o+1] = __float2half_rn(v.y);
    g_w1[o+2] = __float2half_rn(v.z);
    g_w1[o+3] = __float2half_rn(v.w);
}

__global__ void pack_w2_kernel(const float* __restrict__ W2l,
                               const float* __restrict__ W2r) {
    int i4 = blockIdx.x * blockDim.x + threadIdx.x;          // over DOUT*N2/4
    if (i4 >= DOUT * N2 / 4) return;
    int k = i4 / (N2 / 4);
    int c = (i4 % (N2 / 4)) * 4;
    const float* W = (c < 256) ? W2l : W2r;
    int cc = c & 255;
    float4 v = *reinterpret_cast<const float4*>(W + (size_t)k * 256 + cc);
    size_t o = (size_t)k * N2 + c;
    g_w2[o+0] = __float2half_rn(v.x);
    g_w2[o+1] = __float2half_rn(v.y);
    g_w2[o+2] = __float2half_rn(v.z);
    g_w2[o+3] = __float2half_rn(v.w);
}

// ---------------- fp16 tensor-core GEMM --------------------------------------
// Y[M,N] = A[M,K] @ B[K,N], fp16 operands, fp32 accumulate.
// CTA 128x256, BK=32, 8 warps (2M x 4N), warp tile 64x64, 3-stage cp.async.
#define GBM 128
#define GBN 256
#define GBK 32
#define LDA 40      // 32 + 8 pad (halfs)
#define LDB 264     // 256 + 8 pad
#define STG_A (128 * LDA)
#define STG_B (32 * LDB)
#define STAGE_ELEMS (STG_A + STG_B)
#define NSTAGE 3
#define GEMM_SMEM_BYTES (NSTAGE * STAGE_ELEMS * 2)

__device__ __forceinline__ void gemm_load_stage(
    __half* st,
    const __half* __restrict__ A, const __half* __restrict__ B,
    int bm, int bn, int k0, int K, int N, int tid)
{
    __half* sA = st;
    __half* sB = st + STG_A;
    // A: 128x32 halfs = 512 x 16B chunks; 2 per thread
#pragma unroll
    for (int c = 0; c < 2; c++) {
        int idx = tid + c * 256;
        int row = idx >> 2;
        int col = (idx & 3) * 8;
        size_t g = (size_t)(bm + row) * K + k0 + col;
        cp16(sA + row * LDA + col, A + g);
    }
    // B: 32x256 halfs = 1024 chunks; 4 per thread
#pragma unroll
    for (int c = 0; c < 4; c++) {
        int idx = tid + c * 256;
        int row = idx >> 5;
        int col = (idx & 31) * 8;
        size_t g = (size_t)(k0 + row) * N + bn + col;
        cp16(sB + row * LDB + col, B + g);
    }
    asm volatile("cp.async.commit_group;\n");
}

__global__ __launch_bounds__(256, 1)
void gemm_h16(const __half* __restrict__ A,
              const __half* __restrict__ B,
              float* __restrict__ Y, int K, int N)
{
    extern __shared__ __half smem[];
    const int tid = threadIdx.x;
    const int bm = blockIdx.y * GBM;
    const int bn = blockIdx.x * GBN;
    const int warp = tid >> 5;
    const int wm = (warp >> 2) * 64;   // 0 or 64
    const int wn = (warp & 3) * 64;    // 0..192

    wmma::fragment<wmma::accumulator, 16, 16, 16, float> acc[4][4];
#pragma unroll
    for (int i = 0; i < 4; i++)
#pragma unroll
        for (int j = 0; j < 4; j++) wmma::fill_fragment(acc[i][j], 0.f);

    const int KT = K / GBK;
    gemm_load_stage(smem + 0 * STAGE_ELEMS, A, B, bm, bn, 0,   K, N, tid);
    gemm_load_stage(smem + 1 * STAGE_ELEMS, A, B, bm, bn, GBK, K, N, tid);

    for (int kt = 0; kt < KT; kt++) {
        if (kt + 1 < KT) asm volatile("cp.async.wait_group 1;\n" ::: "memory");
        else             asm volatile("cp.async.wait_group 0;\n" ::: "memory");
        __syncthreads();
        if (kt + 2 < KT)
            gemm_load_stage(smem + ((kt + 2) % NSTAGE) * STAGE_ELEMS,
                            A, B, bm, bn, (kt + 2) * GBK, K, N, tid);

        __half* st = smem + (kt % NSTAGE) * STAGE_ELEMS;
        const __half* sA = st;
        const __half* sB = st + STG_A;

#pragma unroll
        for (int ks = 0; ks < 2; ks++) {
            wmma::fragment<wmma::matrix_a, 16, 16, 16, __half, wmma::row_major> fa[4];
#pragma unroll
            for (int i = 0; i < 4; i++)
                wmma::load_matrix_sync(fa[i], sA + (wm + i * 16) * LDA + ks * 16, LDA);
#pragma unroll
            for (int j = 0; j < 4; j++) {
                wmma::fragment<wmma::matrix_b, 16, 16, 16, __half, wmma::row_major> fb;
                wmma::load_matrix_sync(fb, sB + ks * 16 * LDB + wn + j * 16, LDB);
#pragma unroll
                for (int i = 0; i < 4; i++)
                    wmma::mma_sync(acc[i][j], fa[i], fb, acc[i][j]);
            }
        }
    }

#pragma unroll
    for (int i = 0; i < 4; i++)
#pragma unroll
        for (int j = 0; j < 4; j++)
            wmma::store_matrix_sync(Y + (size_t)(bm + wm + i * 16) * N + bn + wn + j * 16,
                                    acc[i][j], N, wmma::mem_row_major);
}

// ---------------- CSR build --------------------------------------------------
__global__ void zero_deg_kernel() {
    int i = blockIdx.x * blockDim.x + threadIdx.x;
    if (i < NP) g_deg[i] = 0;
}

__global__ void count_deg_kernel(const int* __restrict__ dst) {
    int e = blockIdx.x * blockDim.x + threadIdx.x;
    if (e < NE) atomicAdd(&g_deg[dst[e]], 1);
}

__global__ void build_offsets_kernel() {
    __shared__ int ssum[1024];
    const int tid = threadIdx.x;
    const int CHK = (NP + 1023) / 1024;
    int start = tid * CHK;
    int end = start + CHK; if (end > NP) end = NP;
    if (start > NP) start = NP;

    int s = 0;
    for (int i = start; i < end; i++) s += g_deg[i];
    ssum[tid] = s;
    __syncthreads();
    for (int o = 1; o < 1024; o <<= 1) {
        int v = (tid >= o) ? ssum[tid - o] : 0;
        __syncthreads();
        ssum[tid] += v;
        __syncthreads();
    }
    int run = (tid == 0) ? 0 : ssum[tid - 1];
    for (int i = start; i < end; i++) {
        g_off[i] = run;
        g_cur[i] = run;
        run += g_deg[i];
    }
    if (tid == 1023) g_off[NP] = ssum[1023];
}

__global__ void scatter_edges_kernel(const int* __restrict__ src,
                                     const int* __restrict__ dst) {
    int e = blockIdx.x * blockDim.x + threadIdx.x;
    if (e < NE) {
        int d = dst[e];
        int pos = atomicAdd(&g_cur[d], 1);
        g_srcs[pos] = src[e];
    }
}

// ---------------- fused GATv2 gather + softmax + LN/ELU epilogue -------------
__device__ __forceinline__ void gat_core(const float* __restrict__ xl,
                                         const float* __restrict__ xr, int ld,
                                         const float* __restrict__ bl,
                                         const float* __restrict__ br,
                                         const float* __restrict__ att,
                                         const float* __restrict__ bias,
                                         int i, int lane, float* v /*out[8]*/) {
    const int cbase = lane * 8;
    float xri[8], atv[8], blv[8];
    {
        float4 a0 = *reinterpret_cast<const float4*>(xr + (size_t)i * ld + cbase);
        float4 a1 = *reinterpret_cast<const float4*>(xr + (size_t)i * ld + cbase + 4);
        float4 r0 = *reinterpret_cast<const float4*>(br + cbase);
        float4 r1 = *reinterpret_cast<const float4*>(br + cbase + 4);
        xri[0]=a0.x+r0.x; xri[1]=a0.y+r0.y; xri[2]=a0.z+r0.z; xri[3]=a0.w+r0.w;
        xri[4]=a1.x+r1.x; xri[5]=a1.y+r1.y; xri[6]=a1.z+r1.z; xri[7]=a1.w+r1.w;
        float4 t0 = *reinterpret_cast<const float4*>(att + cbase);
        float4 t1 = *reinterpret_cast<const float4*>(att + cbase + 4);
        atv[0]=t0.x; atv[1]=t0.y; atv[2]=t0.z; atv[3]=t0.w;
        atv[4]=t1.x; atv[5]=t1.y; atv[6]=t1.z; atv[7]=t1.w;
        float4 l0 = *reinterpret_cast<const float4*>(bl + cbase);
        float4 l1 = *reinterpret_cast<const float4*>(bl + cbase + 4);
        blv[0]=l0.x; blv[1]=l0.y; blv[2]=l0.z; blv[3]=l0.w;
        blv[4]=l1.x; blv[5]=l1.y; blv[6]=l1.z; blv[7]=l1.w;
    }

    float m = -CUDART_INF_F;
    float s = 0.f;
    float acc[8];
#pragma unroll
    for (int k = 0; k < 8; k++) acc[k] = 0.f;

    const int beg = g_off[i];
    const int end = g_off[i + 1];

    int j = i;           // self loop first
    int ptr = beg;
    while (true) {
        float xlj[8];
        {
            float4 a0 = *reinterpret_cast<const float4*>(xl + (size_t)j * ld + cbase);
            float4 a1 = *reinterpret_cast<const float4*>(xl + (size_t)j * ld + cbase + 4);
            xlj[0]=a0.x+blv[0]; xlj[1]=a0.y+blv[1]; xlj[2]=a0.z+blv[2]; xlj[3]=a0.w+blv[3];
            xlj[4]=a1.x+blv[4]; xlj[5]=a1.y+blv[5]; xlj[6]=a1.z+blv[6]; xlj[7]=a1.w+blv[7];
        }
        float p = 0.f;
#pragma unroll
        for (int k = 0; k < 8; k++) {
            float t = xlj[k] + xri[k];
            t = (t > 0.f) ? t : NEG_SLOPE * t;
            p = fmaf(atv[k], t, p);
        }
        p += __shfl_xor_sync(0xffffffffu, p, 8, 16);
        p += __shfl_xor_sync(0xffffffffu, p, 4, 16);
        p += __shfl_xor_sync(0xffffffffu, p, 2, 16);
        p += __shfl_xor_sync(0xffffffffu, p, 1, 16);

        float e  = p;
        float nm = fmaxf(m, e);
        float sc = __expf(m - nm);
        float wgt = __expf(e - nm);
        s = s * sc + wgt;
#pragma unroll
        for (int k = 0; k < 8; k++) acc[k] = fmaf(acc[k], sc, wgt * xlj[k]);
        m = nm;

        if (ptr >= end) break;
        j = g_srcs[ptr++];
    }

    float inv = 1.f / s;
#pragma unroll
    for (int k = 0; k < 8; k++)
        v[k] = acc[k] * inv + bias[lane * 8 + k];
}

__device__ __forceinline__ void ln_elu_inplace(float* v,
                                               const float* __restrict__ g,
                                               const float* __restrict__ b,
                                               int lane) {
    float s = 0.f, s2 = 0.f;
#pragma unroll
    for (int k = 0; k < 8; k++) { s += v[k]; s2 = fmaf(v[k], v[k], s2); }
#pragma unroll
    for (int o = 16; o >= 1; o >>= 1) {
        s  += __shfl_xor_sync(0xffffffffu, s,  o);
        s2 += __shfl_xor_sync(0xffffffffu, s2, o);
    }
    float mu  = s * (1.f / 256.f);
    float var = s2 * (1.f / 256.f) - mu * mu;
    float rs  = rsqrtf(var + 1e-5f);
#pragma unroll
    for (int k = 0; k < 8; k++) {
        int c = lane * 8 + k;
        float t = (v[k] - mu) * rs * g[c] + b[c];
        v[k] = (t > 0.f) ? t : expm1f(t);
    }
}

// layer 1: gather -> LN -> ELU -> + residual -> h1 (fp32 + fp16); pad rows zeroed
__global__ void gat1_kernel(const float* __restrict__ y1,
                            const float* __restrict__ bl,
                            const float* __restrict__ br,
                            const float* __restrict__ att,
                            const float* __restrict__ bias,
                            const float* __restrict__ resb,
                            const float* __restrict__ lng,
                            const float* __restrict__ lnb,
                            float* __restrict__ h1,
                            __half* __restrict__ h116) {
    int w = (blockIdx.x * blockDim.x + threadIdx.x) >> 5;
    int lane = threadIdx.x & 31;
    if (w >= MPAD) return;
    const int cbase = lane * 8;
    if (w >= NP) {      // zero the GEMM2 pad rows
#pragma unroll
        for (int k = 0; k < 8; k++)
            h116[(size_t)w * DOUT + cbase + k] = __float2half_rn(0.f);
        return;
    }
    float v[8];
    gat_core(y1 + 0, y1 + 256, N1, bl, br, att, bias, w, lane, v);
    ln_elu_inplace(v, lng, lnb, lane);
    const float* res = y1 + 512;
#pragma unroll
    for (int k = 0; k < 8; k++) {
        int c = cbase + k;
        size_t idx = (size_t)w * DOUT + c;
        float hv = v[k] + res[(size_t)w * N1 + c] + resb[c];
        h1[idx] = hv;
        h116[idx] = __float2half_rn(hv);
    }
}

// layer 2: gather -> LN -> ELU -> + h1 -> JK max
__global__ void gat2_kernel(const float* __restrict__ y2,
                            const float* __restrict__ bl,
                            const float* __restrict__ br,
                            const float* __restrict__ att,
                            const float* __restrict__ bias,
                            const float* __restrict__ lng,
                            const float* __restrict__ lnb,
                            const float* __restrict__ h1,
                            float* __restrict__ out) {
    int w = (blockIdx.x * blockDim.x + threadIdx.x) >> 5;
    int lane = threadIdx.x & 31;
    if (w >= NP) return;
    float v[8];
    gat_core(y2 + 0, y2 + 256, N2, bl, br, att, bias, w, lane, v);
    ln_elu_inplace(v, lng, lnb, lane);
    const int cbase = lane * 8;
#pragma unroll
    for (int k = 0; k < 8; k++) {
        size_t idx = (size_t)w * DOUT + cbase + k;
        float h1v = h1[idx];
        out[idx] = fmaxf(h1v, v[k] + h1v);
    }
}

// ---------------- launch -----------------------------------------------------
extern "C" void kernel_launch(void* const* d_in, const int* in_sizes, int n_in,
                              void* d_out, int out_size) {
    const float* x     = (const float*)d_in[0];
    const int*   ei    = (const int*)  d_in[1];
    const float* W1l   = (const float*)d_in[2];
    const float* b1l   = (const float*)d_in[3];
    const float* W1r   = (const float*)d_in[4];
    const float* b1r   = (const float*)d_in[5];
    const float* att1  = (const float*)d_in[6];
    const float* bias1 = (const float*)d_in[7];
    const float* W2l   = (const float*)d_in[8];
    const float* b2l   = (const float*)d_in[9];
    const float* W2r   = (const float*)d_in[10];
    const float* b2r   = (const float*)d_in[11];
    const float* att2  = (const float*)d_in[12];
    const float* bias2 = (const float*)d_in[13];
    const float* ln1g  = (const float*)d_in[14];
    const float* ln1b  = (const float*)d_in[15];
    const float* ln2g  = (const float*)d_in[16];
    const float* ln2b  = (const float*)d_in[17];
    const float* resW  = (const float*)d_in[18];
    const float* resb  = (const float*)d_in[19];
    float* out = (float*)d_out;

    const int* e_src = ei;
    const int* e_dst = ei + NE;

    __half *x16, *w1, *w2, *h116;
    float *y1, *y2, *h1;
    cudaGetSymbolAddress((void**)&x16,  g_x16);
    cudaGetSymbolAddress((void**)&w1,   g_w1);
    cudaGetSymbolAddress((void**)&w2,   g_w2);
    cudaGetSymbolAddress((void**)&h116, g_h116);
    cudaGetSymbolAddress((void**)&y1,   g_y1);
    cudaGetSymbolAddress((void**)&y2,   g_y2);
    cudaGetSymbolAddress((void**)&h1,   g_h1);

    cudaFuncSetAttribute(gemm_h16, cudaFuncAttributeMaxDynamicSharedMemorySize,
                         GEMM_SMEM_BYTES);

    // input conversions
    {
        size_t tot = (size_t)MPAD * DIN / 4;
        convert_x_kernel<<<(unsigned)((tot + 255) / 256), 256>>>(x);
    }
    pack_w1_kernel<<<(DIN * N1 / 4 + 255) / 256, 256>>>(W1l, W1r, resW);
    pack_w2_kernel<<<(DOUT * N2 / 4 + 255) / 256, 256>>>(W2l, W2r);

    // CSR build
    zero_deg_kernel<<<(NP + 255) / 256, 256>>>();
    count_deg_kernel<<<(NE + 255) / 256, 256>>>(e_dst);
    build_offsets_kernel<<<1, 1024>>>();
    scatter_edges_kernel<<<(NE + 255) / 256, 256>>>(e_src, e_dst);

    // layer-1 fused GEMM: y1 = x @ [W1l|W1r|resW]
    gemm_h16<<<dim3(N1 / GBN, MPAD / GBM), 256, GEMM_SMEM_BYTES>>>(
        x16, w1, y1, DIN, N1);

    // layer-1 gather + LN/ELU/residual (fused; also zeroes pad rows)
    int gather1Blocks = (MPAD * 32 + 255) / 256;
    int gather2Blocks = (NP * 32 + 255) / 256;
    gat1_kernel<<<gather1Blocks, 256>>>(y1, b1l, b1r, att1, bias1, resb,
                                        ln1g, ln1b, h1, h116);

    // layer-2 fused GEMM: y2 = h1 @ [W2l|W2r]
    gemm_h16<<<dim3(N2 / GBN, MPAD / GBM), 256, GEMM_SMEM_BYTES>>>(
        h116, w2, y2, DOUT, N2);

    // layer-2 gather + LN/ELU + JK-max (fused)
    gat2_kernel<<<gather2Blocks, 256>>>(y2, b2l, b2r, att2, bias2,
                                        ln2g, ln2b, h1, out);
}

// round 7
// speedup vs baseline: 4.5407x; 1.0421x over previous
#include <cuda_runtime.h>
#include <cuda_fp16.h>
#include <mma.h>
#include <math.h>
#include <math_constants.h>
#include <cstdint>

using namespace nvcuda;

#define NP    30000
#define MPAD  30080          // 235 * 128
#define DIN   1536
#define DOUT  256
#define NE    320000
#define NEG_SLOPE 0.2f
#define N1    768            // xl1 | xr1 | res
#define N2    512            // xl2 | xr2

// ---------------- scratch (device globals; no cudaMalloc allowed) -----------
__device__ __align__(256) __half g_x16[(size_t)MPAD * DIN];
__device__ __align__(256) __half g_w1[(size_t)DIN * N1];    // [K, N] fp16
__device__ __align__(256) __half g_w2[(size_t)DOUT * N2];   // [K, N] fp16
__device__ __align__(256) float g_y1[(size_t)MPAD * N1];
__device__ __align__(256) float g_y2[(size_t)MPAD * N2];
__device__ __align__(256) __half g_y1h[(size_t)NP * 512];   // fp16 xl|xr layer1
__device__ __align__(256) __half g_y2h[(size_t)NP * 512];   // fp16 xl|xr layer2
__device__ __align__(256) float g_h1[(size_t)MPAD * DOUT];
__device__ __align__(256) __half g_h116[(size_t)MPAD * DOUT];

__device__ int g_deg[NP];
__device__ int g_off[NP + 1];
__device__ int g_cur[NP];
__device__ int g_srcs[NE];

// ---------------- helpers ----------------------------------------------------
__device__ __forceinline__ void cp16(void* dst, const void* src) {
    unsigned saddr = (unsigned)__cvta_generic_to_shared(dst);
    asm volatile("cp.async.cg.shared.global [%0], [%1], 16;\n" :: "r"(saddr), "l"(src));
}

// ---------------- merged prep kernel ------------------------------------------
// covers: convert_x (T1), pack_w1 (T2), pack_w2 (T3), zero_deg (T4)
#define PREP_T1 ((size_t)MPAD * DIN / 4)
#define PREP_T2 (DIN * N1 / 4)
#define PREP_T3 (DOUT * N2 / 4)
#define PREP_T4 (NP)
#define PREP_TOT (PREP_T1 + PREP_T2 + PREP_T3 + PREP_T4)

__global__ void prep_kernel(const float* __restrict__ x,
                            const float* __restrict__ W1l,
                            const float* __restrict__ W1r,
                            const float* __restrict__ resW,
                            const float* __restrict__ W2l,
                            const float* __restrict__ W2r) {
    size_t id = (size_t)blockIdx.x * blockDim.x + threadIdx.x;
    if (id < PREP_T1) {
        size_t i4 = id;
        size_t row = i4 / (DIN / 4);
        float4 v;
        if (row < NP) v = *reinterpret_cast<const float4*>(x + i4 * 4);
        else          v = make_float4(0.f, 0.f, 0.f, 0.f);
        __half2 h0 = make_half2(__float2half_rn(v.x), __float2half_rn(v.y));
        __half2 h1 = make_half2(__float2half_rn(v.z), __float2half_rn(v.w));
        *reinterpret_cast<__half2*>(g_x16 + i4 * 4)     = h0;
        *reinterpret_cast<__half2*>(g_x16 + i4 * 4 + 2) = h1;
        return;
    }
    id -= PREP_T1;
    if (id < PREP_T2) {
        int i4 = (int)id;
        int k = i4 / (N1 / 4);
        int c = (i4 % (N1 / 4)) * 4;
        const float* W = (c < 256) ? W1l : (c < 512 ? W1r : resW);
        int cc = c & 255;
        float4 v = *reinterpret_cast<const float4*>(W + (size_t)k * 256 + cc);
        size_t o = (size_t)k * N1 + c;
        g_w1[o+0] = __float2half_rn(v.x);
        g_w1[o+1] = __float2half_rn(v.y);
        g_w1[o+2] = __float2half_rn(v.z);
        g_w1[o+3] = __float2half_rn(v.w);
        return;
    }
    id -= PREP_T2;
    if (id < PREP_T3) {
        int i4 = (int)id;
        int k = i4 / (N2 / 4);
        int c = (i4 % (N2 / 4)) * 4;
        const float* W = (c < 256) ? W2l : W2r;
        int cc = c & 255;
        float4 v = *reinterpret_cast<const float4*>(W + (size_t)k * 256 + cc);
        size_t o = (size_t)k * N2 + c;
        g_w2[o+0] = __float2half_rn(v.x);
        g_w2[o+1] = __float2half_rn(v.y);
        g_w2[o+2] = __float2half_rn(v.z);
        g_w2[o+3] = __float2half_rn(v.w);
        return;
    }
    id -= PREP_T3;
    if (id < PREP_T4) g_deg[id] = 0;
}

// ---------------- y -> fp16 converts for the gathers --------------------------
// y1: take cols [0,512) of 768-wide rows -> g_y1h (512-wide)
__global__ void conv_y1h_kernel(const float* __restrict__ y1) {
    size_t i8 = (size_t)blockIdx.x * blockDim.x + threadIdx.x;   // NP*64
    if (i8 >= (size_t)NP * 64) return;
    size_t row = i8 / 64;
    int c = (int)(i8 % 64) * 8;
    const float4* s = reinterpret_cast<const float4*>(y1 + row * N1 + c);
    float4 a = s[0], b = s[1];
    __half2 h[4];
    h[0] = make_half2(__float2half_rn(a.x), __float2half_rn(a.y));
    h[1] = make_half2(__float2half_rn(a.z), __float2half_rn(a.w));
    h[2] = make_half2(__float2half_rn(b.x), __float2half_rn(b.y));
    h[3] = make_half2(__float2half_rn(b.z), __float2half_rn(b.w));
    *reinterpret_cast<uint4*>(g_y1h + row * 512 + c) = *reinterpret_cast<uint4*>(h);
}

// y2: all 512 cols -> g_y2h
__global__ void conv_y2h_kernel(const float* __restrict__ y2) {
    size_t i8 = (size_t)blockIdx.x * blockDim.x + threadIdx.x;   // NP*64
    if (i8 >= (size_t)NP * 64) return;
    size_t row = i8 / 64;
    int c = (int)(i8 % 64) * 8;
    const float4* s = reinterpret_cast<const float4*>(y2 + row * N2 + c);
    float4 a = s[0], b = s[1];
    __half2 h[4];
    h[0] = make_half2(__float2half_rn(a.x), __float2half_rn(a.y));
    h[1] = make_half2(__float2half_rn(a.z), __float2half_rn(a.w));
    h[2] = make_half2(__float2half_rn(b.x), __float2half_rn(b.y));
    h[3] = make_half2(__float2half_rn(b.z), __float2half_rn(b.w));
    *reinterpret_cast<uint4*>(g_y2h + row * 512 + c) = *reinterpret_cast<uint4*>(h);
}

// ---------------- fp16 tensor-core GEMM --------------------------------------
// Y[M,N] = A[M,K] @ B[K,N], fp16 operands, fp32 accumulate.
// CTA 128x256, BK=64, 8 warps (2M x 4N), warp tile 64x64, 3-stage cp.async.
#define GBM 128
#define GBN 256
#define GBK 64
#define LDA 72      // 64 + 8 pad (halfs)
#define LDB 264     // 256 + 8 pad
#define STG_A (128 * LDA)
#define STG_B (64 * LDB)
#define STAGE_ELEMS (STG_A + STG_B)
#define NSTAGE 3
#define GEMM_SMEM_BYTES (NSTAGE * STAGE_ELEMS * 2)

__device__ __forceinline__ void gemm_load_stage(
    __half* st,
    const __half* __restrict__ A, const __half* __restrict__ B,
    int bm, int bn, int k0, int K, int N, int tid)
{
    __half* sA = st;
    __half* sB = st + STG_A;
    // A: 128x64 halfs = 1024 x 16B chunks; 4 per thread
#pragma unroll
    for (int c = 0; c < 4; c++) {
        int idx = tid + c * 256;
        int row = idx >> 3;
        int col = (idx & 7) * 8;
        size_t g = (size_t)(bm + row) * K + k0 + col;
        cp16(sA + row * LDA + col, A + g);
    }
    // B: 64x256 halfs = 2048 chunks; 8 per thread
#pragma unroll
    for (int c = 0; c < 8; c++) {
        int idx = tid + c * 256;
        int row = idx >> 5;
        int col = (idx & 31) * 8;
        size_t g = (size_t)(k0 + row) * N + bn + col;
        cp16(sB + row * LDB + col, B + g);
    }
    asm volatile("cp.async.commit_group;\n");
}

__global__ __launch_bounds__(256, 1)
void gemm_h16(const __half* __restrict__ A,
              const __half* __restrict__ B,
              float* __restrict__ Y, int K, int N)
{
    extern __shared__ __half smem[];
    const int tid = threadIdx.x;
    const int bm = blockIdx.y * GBM;
    const int bn = blockIdx.x * GBN;
    const int warp = tid >> 5;
    const int wm = (warp >> 2) * 64;   // 0 or 64
    const int wn = (warp & 3) * 64;    // 0..192

    wmma::fragment<wmma::accumulator, 16, 16, 16, float> acc[4][4];
#pragma unroll
    for (int i = 0; i < 4; i++)
#pragma unroll
        for (int j = 0; j < 4; j++) wmma::fill_fragment(acc[i][j], 0.f);

    const int KT = K / GBK;
    gemm_load_stage(smem + 0 * STAGE_ELEMS, A, B, bm, bn, 0,   K, N, tid);
    gemm_load_stage(smem + 1 * STAGE_ELEMS, A, B, bm, bn, GBK, K, N, tid);

    for (int kt = 0; kt < KT; kt++) {
        if (kt + 1 < KT) asm volatile("cp.async.wait_group 1;\n" ::: "memory");
        else             asm volatile("cp.async.wait_group 0;\n" ::: "memory");
        __syncthreads();
        if (kt + 2 < KT)
            gemm_load_stage(smem + ((kt + 2) % NSTAGE) * STAGE_ELEMS,
                            A, B, bm, bn, (kt + 2) * GBK, K, N, tid);

        __half* st = smem + (kt % NSTAGE) * STAGE_ELEMS;
        const __half* sA = st;
        const __half* sB = st + STG_A;

#pragma unroll
        for (int ks = 0; ks < 4; ks++) {
            wmma::fragment<wmma::matrix_a, 16, 16, 16, __half, wmma::row_major> fa[4];
#pragma unroll
            for (int i = 0; i < 4; i++)
                wmma::load_matrix_sync(fa[i], sA + (wm + i * 16) * LDA + ks * 16, LDA);
#pragma unroll
            for (int j = 0; j < 4; j++) {
                wmma::fragment<wmma::matrix_b, 16, 16, 16, __half, wmma::row_major> fb;
                wmma::load_matrix_sync(fb, sB + ks * 16 * LDB + wn + j * 16, LDB);
#pragma unroll
                for (int i = 0; i < 4; i++)
                    wmma::mma_sync(acc[i][j], fa[i], fb, acc[i][j]);
            }
        }
    }

#pragma unroll
    for (int i = 0; i < 4; i++)
#pragma unroll
        for (int j = 0; j < 4; j++)
            wmma::store_matrix_sync(Y + (size_t)(bm + wm + i * 16) * N + bn + wn + j * 16,
                                    acc[i][j], N, wmma::mem_row_major);
}

// ---------------- CSR build --------------------------------------------------
__global__ void count_deg_kernel(const int* __restrict__ dst) {
    int e = blockIdx.x * blockDim.x + threadIdx.x;
    if (e < NE) atomicAdd(&g_deg[dst[e]], 1);
}

__global__ void build_offsets_kernel() {
    __shared__ int ssum[1024];
    const int tid = threadIdx.x;
    const int CHK = (NP + 1023) / 1024;
    int start = tid * CHK;
    int end = start + CHK; if (end > NP) end = NP;
    if (start > NP) start = NP;

    int s = 0;
    for (int i = start; i < end; i++) s += g_deg[i];
    ssum[tid] = s;
    __syncthreads();
    for (int o = 1; o < 1024; o <<= 1) {
        int v = (tid >= o) ? ssum[tid - o] : 0;
        __syncthreads();
        ssum[tid] += v;
        __syncthreads();
    }
    int run = (tid == 0) ? 0 : ssum[tid - 1];
    for (int i = start; i < end; i++) {
        g_off[i] = run;
        g_cur[i] = run;
        run += g_deg[i];
    }
    if (tid == 1023) g_off[NP] = ssum[1023];
}

__global__ void scatter_edges_kernel(const int* __restrict__ src,
                                     const int* __restrict__ dst) {
    int e = blockIdx.x * blockDim.x + threadIdx.x;
    if (e < NE) {
        int d = dst[e];
        int pos = atomicAdd(&g_cur[d], 1);
        g_srcs[pos] = src[e];
    }
}

// ---------------- fused GATv2 gather + softmax + LN/ELU epilogue -------------
// fp16 xl/xr rows (layout [row*512]: xl at +0, xr at +256), fp32 math.
__device__ __forceinline__ void load8h(const __half* p, float* f) {
    uint4 u = *reinterpret_cast<const uint4*>(p);
    const __half2* h = reinterpret_cast<const __half2*>(&u);
    float2 t;
    t = __half22float2(h[0]); f[0] = t.x; f[1] = t.y;
    t = __half22float2(h[1]); f[2] = t.x; f[3] = t.y;
    t = __half22float2(h[2]); f[4] = t.x; f[5] = t.y;
    t = __half22float2(h[3]); f[6] = t.x; f[7] = t.y;
}

__device__ __forceinline__ void gat_core(const __half* __restrict__ yh,
                                         const float* __restrict__ bl,
                                         const float* __restrict__ br,
                                         const float* __restrict__ att,
                                         const float* __restrict__ bias,
                                         int i, int lane, float* v /*out[8]*/) {
    const int cbase = lane * 8;
    float xri[8], atv[8], blv[8];
    {
        load8h(yh + (size_t)i * 512 + 256 + cbase, xri);
        float4 r0 = *reinterpret_cast<const float4*>(br + cbase);
        float4 r1 = *reinterpret_cast<const float4*>(br + cbase + 4);
        xri[0]+=r0.x; xri[1]+=r0.y; xri[2]+=r0.z; xri[3]+=r0.w;
        xri[4]+=r1.x; xri[5]+=r1.y; xri[6]+=r1.z; xri[7]+=r1.w;
        float4 t0 = *reinterpret_cast<const float4*>(att + cbase);
        float4 t1 = *reinterpret_cast<const float4*>(att + cbase + 4);
        atv[0]=t0.x; atv[1]=t0.y; atv[2]=t0.z; atv[3]=t0.w;
        atv[4]=t1.x; atv[5]=t1.y; atv[6]=t1.z; atv[7]=t1.w;
        float4 l0 = *reinterpret_cast<const float4*>(bl + cbase);
        float4 l1 = *reinterpret_cast<const float4*>(bl + cbase + 4);
        blv[0]=l0.x; blv[1]=l0.y; blv[2]=l0.z; blv[3]=l0.w;
        blv[4]=l1.x; blv[5]=l1.y; blv[6]=l1.z; blv[7]=l1.w;
    }

    float m = -CUDART_INF_F;
    float s = 0.f;
    float acc[8];
#pragma unroll
    for (int k = 0; k < 8; k++) acc[k] = 0.f;

    const int beg = g_off[i];
    const int end = g_off[i + 1];

    int j = i;           // self loop first
    int ptr = beg;
    while (true) {
        float xlj[8];
        load8h(yh + (size_t)j * 512 + cbase, xlj);
#pragma unroll
        for (int k = 0; k < 8; k++) xlj[k] += blv[k];

        float p = 0.f;
#pragma unroll
        for (int k = 0; k < 8; k++) {
            float t = xlj[k] + xri[k];
            t = (t > 0.f) ? t : NEG_SLOPE * t;
            p = fmaf(atv[k], t, p);
        }
        p += __shfl_xor_sync(0xffffffffu, p, 8, 16);
        p += __shfl_xor_sync(0xffffffffu, p, 4, 16);
        p += __shfl_xor_sync(0xffffffffu, p, 2, 16);
        p += __shfl_xor_sync(0xffffffffu, p, 1, 16);

        float e  = p;
        float nm = fmaxf(m, e);
        float sc = __expf(m - nm);
        float wgt = __expf(e - nm);
        s = s * sc + wgt;
#pragma unroll
        for (int k = 0; k < 8; k++) acc[k] = fmaf(acc[k], sc, wgt * xlj[k]);
        m = nm;

        if (ptr >= end) break;
        j = g_srcs[ptr++];
    }

    float inv = 1.f / s;
#pragma unroll
    for (int k = 0; k < 8; k++)
        v[k] = acc[k] * inv + bias[lane * 8 + k];
}

__device__ __forceinline__ void ln_elu_inplace(float* v,
                                               const float* __restrict__ g,
                                               const float* __restrict__ b,
                                               int lane) {
    float s = 0.f, s2 = 0.f;
#pragma unroll
    for (int k = 0; k < 8; k++) { s += v[k]; s2 = fmaf(v[k], v[k], s2); }
#pragma unroll
    for (int o = 16; o >= 1; o >>= 1) {
        s  += __shfl_xor_sync(0xffffffffu, s,  o);
        s2 += __shfl_xor_sync(0xffffffffu, s2, o);
    }
    float mu  = s * (1.f / 256.f);
    float var = s2 * (1.f / 256.f) - mu * mu;
    float rs  = rsqrtf(var + 1e-5f);
#pragma unroll
    for (int k = 0; k < 8; k++) {
        int c = lane * 8 + k;
        float t = (v[k] - mu) * rs * g[c] + b[c];
        v[k] = (t > 0.f) ? t : expm1f(t);
    }
}

// layer 1: gather -> LN -> ELU -> + residual -> h1 (fp32 + fp16); pad rows zeroed
__global__ void gat1_kernel(const float* __restrict__ y1,
                            const float* __restrict__ bl,
                            const float* __restrict__ br,
                            const float* __restrict__ att,
                            const float* __restrict__ bias,
                            const float* __restrict__ resb,
                            const float* __restrict__ lng,
                            const float* __restrict__ lnb,
                            float* __restrict__ h1,
                            __half* __restrict__ h116) {
    int w = (blockIdx.x * blockDim.x + threadIdx.x) >> 5;
    int lane = threadIdx.x & 31;
    if (w >= MPAD) return;
    const int cbase = lane * 8;
    if (w >= NP) {      // zero the GEMM2 pad rows
#pragma unroll
        for (int k = 0; k < 8; k++)
            h116[(size_t)w * DOUT + cbase + k] = __float2half_rn(0.f);
        return;
    }
    float v[8];
    gat_core(g_y1h, bl, br, att, bias, w, lane, v);
    ln_elu_inplace(v, lng, lnb, lane);
    const float* res = y1 + 512;
#pragma unroll
    for (int k = 0; k < 8; k++) {
        int c = cbase + k;
        size_t idx = (size_t)w * DOUT + c;
        float hv = v[k] + res[(size_t)w * N1 + c] + resb[c];
        h1[idx] = hv;
        h116[idx] = __float2half_rn(hv);
    }
}

// layer 2: gather -> LN -> ELU -> + h1 -> JK max
__global__ void gat2_kernel(const float* __restrict__ bl,
                            const float* __restrict__ br,
                            const float* __restrict__ att,
                            const float* __restrict__ bias,
                            const float* __restrict__ lng,
                            const float* __restrict__ lnb,
                            const float* __restrict__ h1,
                            float* __restrict__ out) {
    int w = (blockIdx.x * blockDim.x + threadIdx.x) >> 5;
    int lane = threadIdx.x & 31;
    if (w >= NP) return;
    float v[8];
    gat_core(g_y2h, bl, br, att, bias, w, lane, v);
    ln_elu_inplace(v, lng, lnb, lane);
    const int cbase = lane * 8;
#pragma unroll
    for (int k = 0; k < 8; k++) {
        size_t idx = (size_t)w * DOUT + cbase + k;
        float h1v = h1[idx];
        out[idx] = fmaxf(h1v, v[k] + h1v);
    }
}

// ---------------- launch -----------------------------------------------------
extern "C" void kernel_launch(void* const* d_in, const int* in_sizes, int n_in,
                              void* d_out, int out_size) {
    const float* x     = (const float*)d_in[0];
    const int*   ei    = (const int*)  d_in[1];
    const float* W1l   = (const float*)d_in[2];
    const float* b1l   = (const float*)d_in[3];
    const float* W1r   = (const float*)d_in[4];
    const float* b1r   = (const float*)d_in[5];
    const float* att1  = (const float*)d_in[6];
    const float* bias1 = (const float*)d_in[7];
    const float* W2l   = (const float*)d_in[8];
    const float* b2l   = (const float*)d_in[9];
    const float* W2r   = (const float*)d_in[10];
    const float* b2r   = (const float*)d_in[11];
    const float* att2  = (const float*)d_in[12];
    const float* bias2 = (const float*)d_in[13];
    const float* ln1g  = (const float*)d_in[14];
    const float* ln1b  = (const float*)d_in[15];
    const float* ln2g  = (const float*)d_in[16];
    const float* ln2b  = (const float*)d_in[17];
    const float* resW  = (const float*)d_in[18];
    const float* resb  = (const float*)d_in[19];
    float* out = (float*)d_out;

    const int* e_src = ei;
    const int* e_dst = ei + NE;

    __half *x16, *w1, *w2, *h116;
    float *y1, *y2, *h1;
    cudaGetSymbolAddress((void**)&x16,  g_x16);
    cudaGetSymbolAddress((void**)&w1,   g_w1);
    cudaGetSymbolAddress((void**)&w2,   g_w2);
    cudaGetSymbolAddress((void**)&h116, g_h116);
    cudaGetSymbolAddress((void**)&y1,   g_y1);
    cudaGetSymbolAddress((void**)&y2,   g_y2);
    cudaGetSymbolAddress((void**)&h1,   g_h1);

    cudaFuncSetAttribute(gemm_h16, cudaFuncAttributeMaxDynamicSharedMemorySize,
                         GEMM_SMEM_BYTES);

    // merged prep: convert_x + pack_w1 + pack_w2 + zero_deg
    {
        size_t blocks = (PREP_TOT + 255) / 256;
        prep_kernel<<<(unsigned)blocks, 256>>>(x, W1l, W1r, resW, W2l, W2r);
    }

    // CSR build
    count_deg_kernel<<<(NE + 255) / 256, 256>>>(e_dst);
    build_offsets_kernel<<<1, 1024>>>();
    scatter_edges_kernel<<<(NE + 255) / 256, 256>>>(e_src, e_dst);

    // layer-1 fused GEMM: y1 = x @ [W1l|W1r|resW]
    gemm_h16<<<dim3(N1 / GBN, MPAD / GBM), 256, GEMM_SMEM_BYTES>>>(
        x16, w1, y1, DIN, N1);
    conv_y1h_kernel<<<(unsigned)(((size_t)NP * 64 + 255) / 256), 256>>>(y1);

    // layer-1 gather + LN/ELU/residual (fused; also zeroes pad rows)
    int gather1Blocks = (MPAD * 32 + 255) / 256;
    int gather2Blocks = (NP * 32 + 255) / 256;
    gat1_kernel<<<gather1Blocks, 256>>>(y1, b1l, b1r, att1, bias1, resb,
                                        ln1g, ln1b, h1, h116);

    // layer-2 fused GEMM: y2 = h1 @ [W2l|W2r]
    gemm_h16<<<dim3(N2 / GBN, MPAD / GBM), 256, GEMM_SMEM_BYTES>>>(
        h116, w2, y2, DOUT, N2);
    conv_y2h_kernel<<<(unsigned)(((size_t)NP * 64 + 255) / 256), 256>>>(y2);

    // layer-2 gather + LN/ELU + JK-max (fused)
    gat2_kernel<<<gather2Blocks, 256>>>(b2l, b2r, att2, bias2,
                                        ln2g, ln2b, h1, out);
}

// round 9
// speedup vs baseline: 4.6660x; 1.0276x over previous
#include <cuda_runtime.h>
#include <cuda_fp16.h>
#include <mma.h>
#include <math.h>
#include <math_constants.h>
#include <cstdint>

using namespace nvcuda;

#define NP    30000
#define MPAD  30080          // 235 * 128
#define DIN   1536
#define DOUT  256
#define NE    320000
#define NEG_SLOPE 0.2f
#define N1    768            // xl1 | xr1 | res
#define N2    512            // xl2 | xr2

// ---------------- scratch (device globals; no cudaMalloc allowed) -----------
__device__ __align__(256) __half g_x16[(size_t)MPAD * DIN];
__device__ __align__(256) __half g_w1[(size_t)DIN * N1];    // [K, N] fp16
__device__ __align__(256) __half g_w2[(size_t)DOUT * N2];   // [K, N] fp16
__device__ __align__(256) __half g_y1h[(size_t)NP * 512];   // fp16 xl|xr layer1
__device__ __align__(256) __half g_y2h[(size_t)NP * 512];   // fp16 xl|xr layer2
__device__ __align__(256) float g_res[(size_t)NP * DOUT];   // fp32 residual proj
__device__ __align__(256) float g_h1[(size_t)NP * DOUT];
__device__ __align__(256) __half g_h116[(size_t)MPAD * DOUT];

__device__ int g_deg[NP];
__device__ int g_off[NP + 1];
__device__ int g_cur[NP];
__device__ int g_srcs[NE];

// ---------------- helpers ----------------------------------------------------
__device__ __forceinline__ void cp16(void* dst, const void* src) {
    unsigned saddr = (unsigned)__cvta_generic_to_shared(dst);
    asm volatile("cp.async.cg.shared.global [%0], [%1], 16;\n" :: "r"(saddr), "l"(src));
}

// ---------------- merged prep kernel ------------------------------------------
// T1: convert x to fp16; T2: pack W1; T3: pack W2; T4: zero g_deg
// (zeroing lives HERE, a separate launch before count_deg — same-kernel zero +
//  atomicAdd raced in R8 and corrupted the CSR)
#define PREP_T1 ((size_t)MPAD * DIN / 4)
#define PREP_T2 (DIN * N1 / 4)
#define PREP_T3 (DOUT * N2 / 4)
#define PREP_T4 (NP)
#define PREP_TOT (PREP_T1 + PREP_T2 + PREP_T3 + PREP_T4)

__global__ void prep_kernel(const float* __restrict__ x,
                            const float* __restrict__ W1l,
                            const float* __restrict__ W1r,
                            const float* __restrict__ resW,
                            const float* __restrict__ W2l,
                            const float* __restrict__ W2r) {
    size_t id = (size_t)blockIdx.x * blockDim.x + threadIdx.x;
    if (id < PREP_T1) {
        size_t i4 = id;
        size_t row = i4 / (DIN / 4);
        float4 v;
        if (row < NP) v = *reinterpret_cast<const float4*>(x + i4 * 4);
        else          v = make_float4(0.f, 0.f, 0.f, 0.f);
        __half2 h0 = make_half2(__float2half_rn(v.x), __float2half_rn(v.y));
        __half2 h1 = make_half2(__float2half_rn(v.z), __float2half_rn(v.w));
        *reinterpret_cast<__half2*>(g_x16 + i4 * 4)     = h0;
        *reinterpret_cast<__half2*>(g_x16 + i4 * 4 + 2) = h1;
        return;
    }
    id -= PREP_T1;
    if (id < PREP_T2) {
        int i4 = (int)id;
        int k = i4 / (N1 / 4);
        int c = (i4 % (N1 / 4)) * 4;
        const float* W = (c < 256) ? W1l : (c < 512 ? W1r : resW);
        int cc = c & 255;
        float4 v = *reinterpret_cast<const float4*>(W + (size_t)k * 256 + cc);
        size_t o = (size_t)k * N1 + c;
        g_w1[o+0] = __float2half_rn(v.x);
        g_w1[o+1] = __float2half_rn(v.y);
        g_w1[o+2] = __float2half_rn(v.z);
        g_w1[o+3] = __float2half_rn(v.w);
        return;
    }
    id -= PREP_T2;
    if (id < PREP_T3) {
        int i4 = (int)id;
        int k = i4 / (N2 / 4);
        int c = (i4 % (N2 / 4)) * 4;
        const float* W = (c < 256) ? W2l : W2r;
        int cc = c & 255;
        float4 v = *reinterpret_cast<const float4*>(W + (size_t)k * 256 + cc);
        size_t o = (size_t)k * N2 + c;
        g_w2[o+0] = __float2half_rn(v.x);
        g_w2[o+1] = __float2half_rn(v.y);
        g_w2[o+2] = __float2half_rn(v.z);
        g_w2[o+3] = __float2half_rn(v.w);
        return;
    }
    id -= PREP_T3;
    if (id < PREP_T4) g_deg[id] = 0;
}

// ---------------- fp16 tensor-core GEMM with fused-format epilogue -----------
// Y[M,N] = A[M,K] @ B[K,N]; output per column block: fp16 (col < nsplit) else fp32.
// CTA 128x256, BK=64, 8 warps (2M x 4N), warp tile 64x64, 3-stage cp.async.
#define GBM 128
#define GBN 256
#define GBK 64
#define LDA 72      // 64 + 8 pad (halfs)
#define LDB 264     // 256 + 8 pad
#define STG_A (128 * LDA)
#define STG_B (64 * LDB)
#define STAGE_ELEMS (STG_A + STG_B)
#define NSTAGE 3
#define GEMM_SMEM_BYTES (NSTAGE * STAGE_ELEMS * 2)
#define LDY 264     // fp32 epilogue pitch; 128*264*4 = 135168 <= GEMM_SMEM_BYTES

__device__ __forceinline__ void gemm_load_stage(
    __half* st,
    const __half* __restrict__ A, const __half* __restrict__ B,
    int bm, int bn, int k0, int K, int N, int tid)
{
    __half* sA = st;
    __half* sB = st + STG_A;
#pragma unroll
    for (int c = 0; c < 4; c++) {
        int idx = tid + c * 256;
        int row = idx >> 3;
        int col = (idx & 7) * 8;
        size_t g = (size_t)(bm + row) * K + k0 + col;
        cp16(sA + row * LDA + col, A + g);
    }
#pragma unroll
    for (int c = 0; c < 8; c++) {
        int idx = tid + c * 256;
        int row = idx >> 5;
        int col = (idx & 31) * 8;
        size_t g = (size_t)(k0 + row) * N + bn + col;
        cp16(sB + row * LDB + col, B + g);
    }
    asm volatile("cp.async.commit_group;\n");
}

__global__ __launch_bounds__(256, 1)
void gemm_h16(const __half* __restrict__ A,
              const __half* __restrict__ B,
              __half* __restrict__ Yh, int ldh,     // fp16 out (cols < nsplit)
              float* __restrict__ Yf,               // fp32 out (cols >= nsplit)
              int nsplit, int K, int N)
{
    extern __shared__ __half smem[];
    const int tid = threadIdx.x;
    const int bm = blockIdx.y * GBM;
    const int bn = blockIdx.x * GBN;
    const int warp = tid >> 5;
    const int wm = (warp >> 2) * 64;   // 0 or 64
    const int wn = (warp & 3) * 64;    // 0..192

    wmma::fragment<wmma::accumulator, 16, 16, 16, float> acc[4][4];
#pragma unroll
    for (int i = 0; i < 4; i++)
#pragma unroll
        for (int j = 0; j < 4; j++) wmma::fill_fragment(acc[i][j], 0.f);

    const int KT = K / GBK;
    gemm_load_stage(smem + 0 * STAGE_ELEMS, A, B, bm, bn, 0,   K, N, tid);
    gemm_load_stage(smem + 1 * STAGE_ELEMS, A, B, bm, bn, GBK, K, N, tid);

    for (int kt = 0; kt < KT; kt++) {
        if (kt + 1 < KT) asm volatile("cp.async.wait_group 1;\n" ::: "memory");
        else             asm volatile("cp.async.wait_group 0;\n" ::: "memory");
        __syncthreads();
        if (kt + 2 < KT)
            gemm_load_stage(smem + ((kt + 2) % NSTAGE) * STAGE_ELEMS,
                            A, B, bm, bn, (kt + 2) * GBK, K, N, tid);

        __half* st = smem + (kt % NSTAGE) * STAGE_ELEMS;
        const __half* sA = st;
        const __half* sB = st + STG_A;

#pragma unroll
        for (int ks = 0; ks < 4; ks++) {
            wmma::fragment<wmma::matrix_a, 16, 16, 16, __half, wmma::row_major> fa[4];
#pragma unroll
            for (int i = 0; i < 4; i++)
                wmma::load_matrix_sync(fa[i], sA + (wm + i * 16) * LDA + ks * 16, LDA);
#pragma unroll
            for (int j = 0; j < 4; j++) {
                wmma::fragment<wmma::matrix_b, 16, 16, 16, __half, wmma::row_major> fb;
                wmma::load_matrix_sync(fb, sB + ks * 16 * LDB + wn + j * 16, LDB);
#pragma unroll
                for (int i = 0; i < 4; i++)
                    wmma::mma_sync(acc[i][j], fa[i], fb, acc[i][j]);
            }
        }
    }

    // ---- fused-format epilogue via smem staging ----
    __syncthreads();                         // all stage reads complete
    float* sY = reinterpret_cast<float*>(smem);
#pragma unroll
    for (int i = 0; i < 4; i++)
#pragma unroll
        for (int j = 0; j < 4; j++)
            wmma::store_matrix_sync(sY + (wm + i * 16) * LDY + wn + j * 16,
                                    acc[i][j], LDY, wmma::mem_row_major);
    __syncthreads();

    const bool f16 = (bn < nsplit);
#pragma unroll
    for (int c = 0; c < 16; c++) {
        int idx = tid + c * 256;             // 4096 chunks of 8 cols
        int row = idx >> 5;
        int col = (idx & 31) * 8;
        int grow = bm + row;
        if (grow >= NP) continue;            // pad rows never consumed
        const float* src = sY + row * LDY + col;
        float4 v0 = *reinterpret_cast<const float4*>(src);
        float4 v1 = *reinterpret_cast<const float4*>(src + 4);
        if (f16) {
            __half2 h[4];
            h[0] = make_half2(__float2half_rn(v0.x), __float2half_rn(v0.y));
            h[1] = make_half2(__float2half_rn(v0.z), __float2half_rn(v0.w));
            h[2] = make_half2(__float2half_rn(v1.x), __float2half_rn(v1.y));
            h[3] = make_half2(__float2half_rn(v1.z), __float2half_rn(v1.w));
            *reinterpret_cast<uint4*>(Yh + (size_t)grow * ldh + bn + col) =
                *reinterpret_cast<uint4*>(h);
        } else {
            float* dst = Yf + (size_t)grow * DOUT + (bn - nsplit) + col;
            *reinterpret_cast<float4*>(dst)     = v0;
            *reinterpret_cast<float4*>(dst + 4) = v1;
        }
    }
}

// ---------------- CSR build --------------------------------------------------
__global__ void count_deg_kernel(const int* __restrict__ dst) {
    int e = blockIdx.x * blockDim.x + threadIdx.x;
    if (e < NE) atomicAdd(&g_deg[dst[e]], 1);
}

__global__ void build_offsets_kernel() {
    __shared__ int ssum[1024];
    const int tid = threadIdx.x;
    const int CHK = (NP + 1023) / 1024;
    int start = tid * CHK;
    int end = start + CHK; if (end > NP) end = NP;
    if (start > NP) start = NP;

    int s = 0;
    for (int i = start; i < end; i++) s += g_deg[i];
    ssum[tid] = s;
    __syncthreads();
    for (int o = 1; o < 1024; o <<= 1) {
        int v = (tid >= o) ? ssum[tid - o] : 0;
        __syncthreads();
        ssum[tid] += v;
        __syncthreads();
    }
    int run = (tid == 0) ? 0 : ssum[tid - 1];
    for (int i = start; i < end; i++) {
        g_off[i] = run;
        g_cur[i] = run;
        run += g_deg[i];
    }
    if (tid == 1023) g_off[NP] = ssum[1023];
}

__global__ void scatter_edges_kernel(const int* __restrict__ src,
                                     const int* __restrict__ dst) {
    int e = blockIdx.x * blockDim.x + threadIdx.x;
    if (e < NE) {
        int d = dst[e];
        int pos = atomicAdd(&g_cur[d], 1);
        g_srcs[pos] = src[e];
    }
}

// ---------------- fused GATv2 gather + softmax + LN/ELU epilogue -------------
__device__ __forceinline__ void load8h(const __half* p, float* f) {
    uint4 u = *reinterpret_cast<const uint4*>(p);
    const __half2* h = reinterpret_cast<const __half2*>(&u);
    float2 t;
    t = __half22float2(h[0]); f[0] = t.x; f[1] = t.y;
    t = __half22float2(h[1]); f[2] = t.x; f[3] = t.y;
    t = __half22float2(h[2]); f[4] = t.x; f[5] = t.y;
    t = __half22float2(h[3]); f[6] = t.x; f[7] = t.y;
}

__device__ __forceinline__ void gat_core(const __half* __restrict__ yh,
                                         const float* __restrict__ bl,
                                         const float* __restrict__ br,
                                         const float* __restrict__ att,
                                         const float* __restrict__ bias,
                                         int i, int lane, float* v /*out[8]*/) {
    const int cbase = lane * 8;
    float xri[8], atv[8], blv[8];
    {
        load8h(yh + (size_t)i * 512 + 256 + cbase, xri);
        float4 r0 = *reinterpret_cast<const float4*>(br + cbase);
        float4 r1 = *reinterpret_cast<const float4*>(br + cbase + 4);
        xri[0]+=r0.x; xri[1]+=r0.y; xri[2]+=r0.z; xri[3]+=r0.w;
        xri[4]+=r1.x; xri[5]+=r1.y; xri[6]+=r1.z; xri[7]+=r1.w;
        float4 t0 = *reinterpret_cast<const float4*>(att + cbase);
        float4 t1 = *reinterpret_cast<const float4*>(att + cbase + 4);
        atv[0]=t0.x; atv[1]=t0.y; atv[2]=t0.z; atv[3]=t0.w;
        atv[4]=t1.x; atv[5]=t1.y; atv[6]=t1.z; atv[7]=t1.w;
        float4 l0 = *reinterpret_cast<const float4*>(bl + cbase);
        float4 l1 = *reinterpret_cast<const float4*>(bl + cbase + 4);
        blv[0]=l0.x; blv[1]=l0.y; blv[2]=l0.z; blv[3]=l0.w;
        blv[4]=l1.x; blv[5]=l1.y; blv[6]=l1.z; blv[7]=l1.w;
    }

    float m = -CUDART_INF_F;
    float s = 0.f;
    float acc[8];
#pragma unroll
    for (int k = 0; k < 8; k++) acc[k] = 0.f;

    const int beg = g_off[i];
    const int end = g_off[i + 1];

    int j = i;           // self loop first
    int ptr = beg;
    while (true) {
        float xlj[8];
        load8h(yh + (size_t)j * 512 + cbase, xlj);
#pragma unroll
        for (int k = 0; k < 8; k++) xlj[k] += blv[k];

        float p = 0.f;
#pragma unroll
        for (int k = 0; k < 8; k++) {
            float t = xlj[k] + xri[k];
            t = (t > 0.f) ? t : NEG_SLOPE * t;
            p = fmaf(atv[k], t, p);
        }
        p += __shfl_xor_sync(0xffffffffu, p, 8, 16);
        p += __shfl_xor_sync(0xffffffffu, p, 4, 16);
        p += __shfl_xor_sync(0xffffffffu, p, 2, 16);
        p += __shfl_xor_sync(0xffffffffu, p, 1, 16);

        float e  = p;
        float nm = fmaxf(m, e);
        float sc = __expf(m - nm);
        float wgt = __expf(e - nm);
        s = s * sc + wgt;
#pragma unroll
        for (int k = 0; k < 8; k++) acc[k] = fmaf(acc[k], sc, wgt * xlj[k]);
        m = nm;

        if (ptr >= end) break;
        j = g_srcs[ptr++];
    }

    float inv = 1.f / s;
#pragma unroll
    for (int k = 0; k < 8; k++)
        v[k] = acc[k] * inv + bias[lane * 8 + k];
}

__device__ __forceinline__ void ln_elu_inplace(float* v,
                                               const float* __restrict__ g,
                                               const float* __restrict__ b,
                                               int lane) {
    float s = 0.f, s2 = 0.f;
#pragma unroll
    for (int k = 0; k < 8; k++) { s += v[k]; s2 = fmaf(v[k], v[k], s2); }
#pragma unroll
    for (int o = 16; o >= 1; o >>= 1) {
        s  += __shfl_xor_sync(0xffffffffu, s,  o);
        s2 += __shfl_xor_sync(0xffffffffu, s2, o);
    }
    float mu  = s * (1.f / 256.f);
    float var = s2 * (1.f / 256.f) - mu * mu;
    float rs  = rsqrtf(var + 1e-5f);
#pragma unroll
    for (int k = 0; k < 8; k++) {
        int c = lane * 8 + k;
        float t = (v[k] - mu) * rs * g[c] + b[c];
        v[k] = (t > 0.f) ? t : expm1f(t);
    }
}

// layer 1: gather -> LN -> ELU -> + residual -> h1 (fp32 + fp16); pad rows zeroed
__global__ void gat1_kernel(const float* __restrict__ res,
                            const float* __restrict__ bl,
                            const float* __restrict__ br,
                            const float* __restrict__ att,
                            const float* __restrict__ bias,
                            const float* __restrict__ resb,
                            const float* __restrict__ lng,
                            const float* __restrict__ lnb,
                            float* __restrict__ h1,
                            __half* __restrict__ h116) {
    int w = (blockIdx.x * blockDim.x + threadIdx.x) >> 5;
    int lane = threadIdx.x & 31;
    if (w >= MPAD) return;
    const int cbase = lane * 8;
    if (w >= NP) {      // zero the GEMM2 pad rows
#pragma unroll
        for (int k = 0; k < 8; k++)
            h116[(size_t)w * DOUT + cbase + k] = __float2half_rn(0.f);
        return;
    }
    float v[8];
    gat_core(g_y1h, bl, br, att, bias, w, lane, v);
    ln_elu_inplace(v, lng, lnb, lane);
#pragma unroll
    for (int k = 0; k < 8; k++) {
        int c = cbase + k;
        size_t idx = (size_t)w * DOUT + c;
        float hv = v[k] + res[idx] + resb[c];
        h1[idx] = hv;
        h116[idx] = __float2half_rn(hv);
    }
}

// layer 2: gather -> LN -> ELU -> + h1 -> JK max
__global__ void gat2_kernel(const float* __restrict__ bl,
                            const float* __restrict__ br,
                            const float* __restrict__ att,
                            const float* __restrict__ bias,
                            const float* __restrict__ lng,
                            const float* __restrict__ lnb,
                            const float* __restrict__ h1,
                            float* __restrict__ out) {
    int w = (blockIdx.x * blockDim.x + threadIdx.x) >> 5;
    int lane = threadIdx.x & 31;
    if (w >= NP) return;
    float v[8];
    gat_core(g_y2h, bl, br, att, bias, w, lane, v);
    ln_elu_inplace(v, lng, lnb, lane);
    const int cbase = lane * 8;
#pragma unroll
    for (int k = 0; k < 8; k++) {
        size_t idx = (size_t)w * DOUT + cbase + k;
        float h1v = h1[idx];
        out[idx] = fmaxf(h1v, v[k] + h1v);
    }
}

// ---------------- launch -----------------------------------------------------
extern "C" void kernel_launch(void* const* d_in, const int* in_sizes, int n_in,
                              void* d_out, int out_size) {
    const float* x     = (const float*)d_in[0];
    const int*   ei    = (const int*)  d_in[1];
    const float* W1l   = (const float*)d_in[2];
    const float* b1l   = (const float*)d_in[3];
    const float* W1r   = (const float*)d_in[4];
    const float* b1r   = (const float*)d_in[5];
    const float* att1  = (const float*)d_in[6];
    const float* bias1 = (const float*)d_in[7];
    const float* W2l   = (const float*)d_in[8];
    const float* b2l   = (const float*)d_in[9];
    const float* W2r   = (const float*)d_in[10];
    const float* b2r   = (const float*)d_in[11];
    const float* att2  = (const float*)d_in[12];
    const float* bias2 = (const float*)d_in[13];
    const float* ln1g  = (const float*)d_in[14];
    const float* ln1b  = (const float*)d_in[15];
    const float* ln2g  = (const float*)d_in[16];
    const float* ln2b  = (const float*)d_in[17];
    const float* resW  = (const float*)d_in[18];
    const float* resb  = (const float*)d_in[19];
    float* out = (float*)d_out;

    const int* e_src = ei;
    const int* e_dst = ei + NE;

    __half *x16, *w1, *w2, *h116, *y1h, *y2h;
    float *res, *h1;
    cudaGetSymbolAddress((void**)&x16,  g_x16);
    cudaGetSymbolAddress((void**)&w1,   g_w1);
    cudaGetSymbolAddress((void**)&w2,   g_w2);
    cudaGetSymbolAddress((void**)&h116, g_h116);
    cudaGetSymbolAddress((void**)&y1h,  g_y1h);
    cudaGetSymbolAddress((void**)&y2h,  g_y2h);
    cudaGetSymbolAddress((void**)&res,  g_res);
    cudaGetSymbolAddress((void**)&h1,   g_h1);

    cudaFuncSetAttribute(gemm_h16, cudaFuncAttributeMaxDynamicSharedMemorySize,
                         GEMM_SMEM_BYTES);

    // prep: convert x + pack weights + zero g_deg (happens-before count_deg)
    prep_kernel<<<(unsigned)((PREP_TOT + 255) / 256), 256>>>(x, W1l, W1r, resW, W2l, W2r);

    // CSR build
    count_deg_kernel<<<(NE + 255) / 256, 256>>>(e_dst);
    build_offsets_kernel<<<1, 1024>>>();
    scatter_edges_kernel<<<(NE + 255) / 256, 256>>>(e_src, e_dst);

    // layer-1 fused GEMM: [xl|xr] -> fp16 g_y1h, res -> fp32 g_res
    gemm_h16<<<dim3(N1 / GBN, MPAD / GBM), 256, GEMM_SMEM_BYTES>>>(
        x16, w1, y1h, 512, res, 512, DIN, N1);

    // layer-1 gather + LN/ELU/residual (fused; also zeroes pad rows)
    int gather1Blocks = (MPAD * 32 + 255) / 256;
    int gather2Blocks = (NP * 32 + 255) / 256;
    gat1_kernel<<<gather1Blocks, 256>>>(res, b1l, b1r, att1, bias1, resb,
                                        ln1g, ln1b, h1, h116);

    // layer-2 fused GEMM: all cols -> fp16 g_y2h
    gemm_h16<<<dim3(N2 / GBN, MPAD / GBM), 256, GEMM_SMEM_BYTES>>>(
        h116, w2, y2h, 512, (float*)nullptr, 512, DOUT, N2);

    // layer-2 gather + LN/ELU + JK-max (fused)
    gat2_kernel<<<gather2Blocks, 256>>>(b2l, b2r, att2, bias2,
                                        ln2g, ln2b, h1, out);
}